// round 13
// baseline (speedup 1.0000x reference)
#include <cuda_runtime.h>
#include <cuda_fp16.h>
#include <math.h>
#include <stdint.h>

// Problem constants
#define Bq 4
#define Tq 2048
#define Cq 2048
#define Hq 32
#define HSq 64
#define Mq (Bq*Tq)            // 8192 tokens
#define DW 128
#define DA 128
#define DG 224
#define DGp 256               // padded K for g lora (BK=64 divisibility)
#define DV 64
#define EPS_GN 0.00064f

// ---------------------------------------------------------------------------
// Scratch (static device globals; zero-initialized at module load)
// ---------------------------------------------------------------------------
#define BTC ((size_t)Mq*Cq)
__device__ __half h_xr[BTC];
__device__ __half h_xw[BTC];
__device__ __half h_xk[BTC];
__device__ __half h_xv[BTC];
__device__ __half h_xa[BTC];
__device__ __half h_xg[BTC];
__device__ __half h_z [BTC];
__device__ __half h_Wr[(size_t)Cq*Cq];
__device__ __half h_Wk[(size_t)Cq*Cq];
__device__ __half h_Wv[(size_t)Cq*Cq];
__device__ __half h_Wo[(size_t)Cq*Cq];
__device__ __half h_w1[(size_t)128*Cq];
__device__ __half h_w2[(size_t)Cq*DW];
__device__ __half h_a1[(size_t)128*Cq];
__device__ __half h_a2[(size_t)Cq*DA];
__device__ __half h_v1[(size_t)128*Cq];
__device__ __half h_v2[(size_t)Cq*DV];
__device__ __half h_g1[(size_t)DGp*Cq];   // pad rows stay 0
__device__ __half h_g2[(size_t)Cq*DGp];   // pad cols stay 0
__device__ __half h_tw[(size_t)Mq*DW];
__device__ __half h_ta[(size_t)Mq*DA];
__device__ __half h_tv[(size_t)Mq*DV];
__device__ __half h_tg[(size_t)Mq*DGp];   // stride 256
// fp32 intermediates
__device__ float g_r [BTC];
__device__ float g_k [BTC];
__device__ float g_v [BTC];
__device__ float g_dec[BTC];
__device__ float g_a [BTC];
__device__ float g_g [BTC];
__device__ float g_kk[BTC];
__device__ float g_y [BTC];

__device__ __forceinline__ float sigmoidf_(float x){ return 1.0f/(1.0f+expf(-x)); }

__device__ __forceinline__ void cpa16(uint32_t s, const void* g){
    asm volatile("cp.async.cg.shared.global [%0], [%1], 16;\n" :: "r"(s), "l"(g));
}
__device__ __forceinline__ void ldsm_x4(uint32_t* r, uint32_t addr){
    asm volatile("ldmatrix.sync.aligned.m8n8.x4.shared.b16 {%0,%1,%2,%3}, [%4];"
        : "=r"(r[0]),"=r"(r[1]),"=r"(r[2]),"=r"(r[3]) : "r"(addr));
}
__device__ __forceinline__ void mma16(float* c, const uint32_t* a, const uint32_t* b){
    asm volatile("mma.sync.aligned.m16n8k16.row.col.f32.f16.f16.f32 "
        "{%0,%1,%2,%3},{%4,%5,%6,%7},{%8,%9},{%0,%1,%2,%3};\n"
        : "+f"(c[0]),"+f"(c[1]),"+f"(c[2]),"+f"(c[3])
        : "r"(a[0]),"r"(a[1]),"r"(a[2]),"r"(a[3]),"r"(b[0]),"r"(b[1]));
}

// ---------------------------------------------------------------------------
// Prep: 4x f32->f16 weight copies in ONE launch (blockIdx.y selects)
// ---------------------------------------------------------------------------
__global__ void f2h4_kernel(const float* __restrict__ i0, __half* __restrict__ o0,
                            const float* __restrict__ i1, __half* __restrict__ o1,
                            const float* __restrict__ i2, __half* __restrict__ o2,
                            const float* __restrict__ i3, __half* __restrict__ o3,
                            size_t n4)
{
    size_t i = (size_t)blockIdx.x*blockDim.x + threadIdx.x;
    if (i >= n4) return;
    const float* in = (blockIdx.y==0)?i0:(blockIdx.y==1)?i1:(blockIdx.y==2)?i2:i3;
    __half* out     = (blockIdx.y==0)?o0:(blockIdx.y==1)?o1:(blockIdx.y==2)?o2:o3;
    float4 v = ((const float4*)in)[i];
    ((__half2*)out)[i*2  ] = __floats2half2_rn(v.x, v.y);
    ((__half2*)out)[i*2+1] = __floats2half2_rn(v.z, v.w);
}

// ---------------------------------------------------------------------------
// 8 lora-weight transposes in ONE launch; out[c2*Rs + r2]
// ---------------------------------------------------------------------------
__device__ __forceinline__
void transpose_body(const float* __restrict__ in, __half* __restrict__ out,
                    int R, int C, int Rs)
{
    __shared__ float tile[32][33];
    int cb = blockIdx.x*32, rb = blockIdx.y*32;
    if (cb >= C || rb >= R) return;
    int c = cb + threadIdx.x;
    #pragma unroll
    for (int i=threadIdx.y; i<32; i+=8){
        int r = rb + i;
        if (r<R && c<C) tile[i][threadIdx.x] = in[(size_t)r*C + c];
    }
    __syncthreads();
    int r2 = rb + threadIdx.x;
    #pragma unroll
    for (int i=threadIdx.y; i<32; i+=8){
        int c2 = cb + i;
        if (r2<R && c2<C) out[(size_t)c2*Rs + r2] = __float2half_rn(tile[threadIdx.x][i]);
    }
}

__global__ void transpose8b(const float* w1, __half* w1h, const float* w2, __half* w2h,
                            const float* a1, __half* a1h, const float* a2, __half* a2h,
                            const float* v1, __half* v1h, const float* v2, __half* v2h,
                            const float* g1, __half* g1h, const float* g2, __half* g2h)
{
    switch(blockIdx.z){
        case 0: transpose_body(w1, w1h, Cq, DW, Cq);  break;
        case 1: transpose_body(w2, w2h, DW, Cq, DW);  break;
        case 2: transpose_body(a1, a1h, Cq, DA, Cq);  break;
        case 3: transpose_body(a2, a2h, DA, Cq, DA);  break;
        case 4: transpose_body(v1, v1h, Cq, DV, Cq);  break;
        case 5: transpose_body(v2, v2h, DV, Cq, DV);  break;
        case 6: transpose_body(g1, g1h, Cq, DG, Cq);  break;
        default: transpose_body(g2, g2h, DG, Cq, DGp); break;
    }
}

// ---------------------------------------------------------------------------
// Token-shift mix -> fp16; 2 independent float4 groups per thread (MLP=4)
// ---------------------------------------------------------------------------
__global__ void mix_kernel(const float* __restrict__ x,
                           const float* __restrict__ cr, const float* __restrict__ cw,
                           const float* __restrict__ ck, const float* __restrict__ cv,
                           const float* __restrict__ ca, const float* __restrict__ cg,
                           __half* __restrict__ xr, __half* __restrict__ xw,
                           __half* __restrict__ xk, __half* __restrict__ xv,
                           __half* __restrict__ xa, __half* __restrict__ xg)
{
    size_t i8 = (size_t)blockIdx.x*blockDim.x + threadIdx.x;   // 8-float group
    size_t n8 = BTC/8;
    if (i8 >= n8) return;
    size_t i4a = i8*2, i4b = i8*2 + 1;       // same token row (8 | 2048)
    int tok = (int)((i4a*4) / Cq);
    int t   = tok % Tq;
    const float4* x4 = (const float4*)x;
    float4 xc0 = x4[i4a], xc1 = x4[i4b];
    float4 xp0, xp1;
    if (t==0){ xp0 = make_float4(0,0,0,0); xp1 = make_float4(0,0,0,0); }
    else     { xp0 = x4[i4a - Cq/4]; xp1 = x4[i4b - Cq/4]; }
    float4 dx0 = make_float4(xp0.x-xc0.x, xp0.y-xc0.y, xp0.z-xc0.z, xp0.w-xc0.w);
    float4 dx1 = make_float4(xp1.x-xc1.x, xp1.y-xc1.y, xp1.z-xc1.z, xp1.w-xc1.w);
    size_t c4a = i4a % (Cq/4), c4b = i4b % (Cq/4);
    #define MIX1(COEF, OUT) { \
        float4 cf0 = ((const float4*)COEF)[c4a]; \
        float4 cf1 = ((const float4*)COEF)[c4b]; \
        ((__half2*)OUT)[i4a*2  ] = __floats2half2_rn(xc0.x + dx0.x*cf0.x, xc0.y + dx0.y*cf0.y); \
        ((__half2*)OUT)[i4a*2+1] = __floats2half2_rn(xc0.z + dx0.z*cf0.z, xc0.w + dx0.w*cf0.w); \
        ((__half2*)OUT)[i4b*2  ] = __floats2half2_rn(xc1.x + dx1.x*cf1.x, xc1.y + dx1.y*cf1.y); \
        ((__half2*)OUT)[i4b*2+1] = __floats2half2_rn(xc1.z + dx1.z*cf1.z, xc1.w + dx1.w*cf1.w); }
    MIX1(cr, xr) MIX1(cw, xw) MIX1(ck, xk) MIX1(cv, xv) MIX1(ca, xa) MIX1(cg, xg)
    #undef MIX1
}

// ---------------------------------------------------------------------------
// Epilogue transform: 0 none, 1 tanh, 2 sigmoid, 3 w->decay, 4 a-sigm, 5 v-mix
// ---------------------------------------------------------------------------
template<int EPI>
__device__ __forceinline__ float epi_val(float val, int m, int n, int Nd,
                                         const float* __restrict__ bias,
                                         const float* __restrict__ vold,
                                         const float* __restrict__ vfirst)
{
    if (EPI==1) { val = tanhf(val); }
    else if (EPI==2) { val = sigmoidf_(val); }
    else if (EPI==3) {
        float w = bias[n] + val;
        float mneg = -w;
        float sp = fmaxf(mneg,0.f) + log1pf(expf(-fabsf(mneg)));
        float wl = -sp - 0.5f;
        val = expf(-expf(wl));
    }
    else if (EPI==4) { val = sigmoidf_(bias[n] + val); }
    else if (EPI==5) {
        float s  = sigmoidf_(bias[n] + val);
        size_t idx = (size_t)m*Nd + n;
        float vo = vold[idx];
        val = vo + (vfirst[idx] - vo)*s;
    }
    return val;
}

// ---------------------------------------------------------------------------
// fp16 tensor-core GEMM body (bm,bn passed in): C[m,n] = sum_k A[m,k]*B[n,k]
// CTA 128x128, BK=64, 3-stage cp.async ring, ONE __syncthreads per slab.
// ---------------------------------------------------------------------------
#define GST 3
#define ST_HB (128*72*2)
#define ST_BYTES (2*ST_HB)

template<int EPI,int RND>
__device__ __forceinline__
void gemm_body(int bm, int bn,
               const __half* __restrict__ A, const __half* __restrict__ Bw,
               void* __restrict__ Cm, int Nd, int Kd,
               const float* __restrict__ bias,
               const float* __restrict__ vold, const float* __restrict__ vfirst)
{
    extern __shared__ __align__(128) char smc[];
    const int tid = threadIdx.x;
    const int lane = tid&31, warp = tid>>5;
    const int wm = (warp&1)*64, wn = (warp>>1)*32;
    const int g = lane>>2, tig = lane&3;
    const uint32_t sbase = (uint32_t)__cvta_generic_to_shared(smc);

    const int arow = wm + (lane&7) + ((lane>>3)&1)*8;
    const int akof = (lane>>4)*8;
    const int brow = wn + (lane&7) + (lane>>4)*8;
    const int bkof = ((lane>>3)&1)*8;

    float acc[4][4][4];
    #pragma unroll
    for (int i=0;i<4;i++)
        #pragma unroll
        for (int j=0;j<4;j++)
            #pragma unroll
            for (int q=0;q<4;q++) acc[i][j][q]=0.f;

    const int NS = Kd >> 6;

    auto loadSlab = [&](int s, int st){
        const uint32_t sb = sbase + st*ST_BYTES;
        const int k0 = s*64;
        #pragma unroll
        for (int i=0;i<4;i++){
            int id  = tid + i*256;
            int row = id>>3, c16 = id&7;
            cpa16(sb + row*144 + c16*16,
                  &A[(size_t)(bm+row)*Kd + k0 + c16*8]);
            cpa16(sb + ST_HB + row*144 + c16*16,
                  &Bw[(size_t)(bn+row)*Kd + k0 + c16*8]);
        }
    };
    auto compute = [&](int st){
        const uint32_t sb = sbase + st*ST_BYTES;
        #pragma unroll
        for (int ks=0; ks<4; ks++){
            uint32_t af[4][4], bf[2][4];
            #pragma unroll
            for (int mt=0;mt<4;mt++)
                ldsm_x4(af[mt], sb + ((arow+mt*16)*72 + akof + ks*16)*2);
            #pragma unroll
            for (int p=0;p<2;p++)
                ldsm_x4(bf[p], sb + ST_HB + ((brow+p*16)*72 + bkof + ks*16)*2);
            #pragma unroll
            for (int mt=0;mt<4;mt++)
                #pragma unroll
                for (int nt=0;nt<4;nt++)
                    mma16(acc[mt][nt], af[mt], &bf[nt>>1][(nt&1)*2]);
        }
    };

    #pragma unroll
    for (int i=0;i<GST-1;i++){
        if (i<NS) loadSlab(i,i);
        asm volatile("cp.async.commit_group;\n");
    }
    int st = 0;
    for (int s=0;s<NS;s++){
        asm volatile("cp.async.wait_group %0;\n" :: "n"(GST-2));
        __syncthreads();
        int ld = s + GST-1;
        if (ld < NS){
            int lst = st + 2; if (lst >= 3) lst -= 3;
            loadSlab(ld, lst);
        }
        asm volatile("cp.async.commit_group;\n");
        compute(st);
        if (++st == 3) st = 0;
    }

    #pragma unroll
    for (int mt=0;mt<4;mt++){
        int r0 = bm + wm + mt*16 + g;
        #pragma unroll
        for (int nt=0;nt<4;nt++){
            int n0 = bn + wn + nt*8 + tig*2;
            if (n0 < Nd){
                float* c = acc[mt][nt];
                float v00 = epi_val<EPI>(c[0], r0,   n0,   Nd, bias, vold, vfirst);
                float v01 = epi_val<EPI>(c[1], r0,   n0+1, Nd, bias, vold, vfirst);
                float v10 = epi_val<EPI>(c[2], r0+8, n0,   Nd, bias, vold, vfirst);
                float v11 = epi_val<EPI>(c[3], r0+8, n0+1, Nd, bias, vold, vfirst);
                if (RND){
                    __half* O = (__half*)Cm;
                    *(__half2*)&O[(size_t)r0*Nd + n0]     = __floats2half2_rn(v00, v01);
                    *(__half2*)&O[(size_t)(r0+8)*Nd + n0] = __floats2half2_rn(v10, v11);
                } else {
                    float* O = (float*)Cm;
                    *(float2*)&O[(size_t)r0*Nd + n0]     = make_float2(v00, v01);
                    *(float2*)&O[(size_t)(r0+8)*Nd + n0] = make_float2(v10, v11);
                }
            }
        }
    }
}

template<int EPI,int RND>
__global__ __launch_bounds__(256,2)
void gemm_h(const __half* __restrict__ A, const __half* __restrict__ Bw,
            void* __restrict__ Cm, int Nd, int Kd,
            const float* __restrict__ bias,
            const float* __restrict__ vold, const float* __restrict__ vfirst)
{
    gemm_body<EPI,RND>(blockIdx.y*128, blockIdx.x*128, A, Bw, Cm, Nd, Kd, bias, vold, vfirst);
}

// merged r/k/v projections
__global__ __launch_bounds__(256,2)
void gemm_h3(const __half* __restrict__ A0, const __half* __restrict__ B0, float* __restrict__ C0,
             const __half* __restrict__ A1, const __half* __restrict__ B1, float* __restrict__ C1,
             const __half* __restrict__ A2, const __half* __restrict__ B2, float* __restrict__ C2)
{
    const __half* A = (blockIdx.z==0) ? A0 : (blockIdx.z==1) ? A1 : A2;
    const __half* B = (blockIdx.z==0) ? B0 : (blockIdx.z==1) ? B1 : B2;
    float*        C = (blockIdx.z==0) ? C0 : (blockIdx.z==1) ? C1 : C2;
    gemm_body<0,0>(blockIdx.y*128, blockIdx.x*128, A, B, (void*)C, Cq, Cq, nullptr, nullptr, nullptr);
}

// 4 lora up-projections in ONE launch
__global__ __launch_bounds__(256,2)
void gemm_lora4(const __half* __restrict__ xw, const __half* __restrict__ w1h, __half* __restrict__ tw,
                const __half* __restrict__ xa, const __half* __restrict__ a1h, __half* __restrict__ ta,
                const __half* __restrict__ xv, const __half* __restrict__ v1h, __half* __restrict__ tv,
                const __half* __restrict__ xg, const __half* __restrict__ g1h, __half* __restrict__ tg)
{
    const int bn = blockIdx.x*128;
    const int bm = blockIdx.y*128;
    switch(blockIdx.z){
        case 0: if (bn >= DW) return; gemm_body<1,1>(bm, bn, xw, w1h, (void*)tw, DW,  Cq, nullptr,nullptr,nullptr); break;
        case 1: if (bn >= DA) return; gemm_body<0,1>(bm, bn, xa, a1h, (void*)ta, DA,  Cq, nullptr,nullptr,nullptr); break;
        case 2: if (bn >= DV) return; gemm_body<0,1>(bm, bn, xv, v1h, (void*)tv, DV,  Cq, nullptr,nullptr,nullptr); break;
        default:                      gemm_body<2,1>(bm, bn, xg, g1h, (void*)tg, DGp, Cq, nullptr,nullptr,nullptr); break;
    }
}

// 3 lora down-projections (dec/a/v) in ONE launch — gate moved into wkv_gate
__global__ __launch_bounds__(256,2)
void gemm_lorad3(const __half* __restrict__ twh, const __half* __restrict__ w2h, float* __restrict__ dec, const float* __restrict__ w0,
                 const __half* __restrict__ tah, const __half* __restrict__ a2h, float* __restrict__ aB,  const float* __restrict__ a0,
                 const __half* __restrict__ tvh, const __half* __restrict__ v2h, float* __restrict__ vB,  const float* __restrict__ v0,
                 const float* __restrict__ vfirst)
{
    const int bn = blockIdx.x*128;
    const int bm = blockIdx.y*128;
    switch(blockIdx.z){
        case 0: gemm_body<3,0>(bm, bn, twh, w2h, (void*)dec, Cq, DW, w0, nullptr, nullptr); break;
        case 1: gemm_body<4,0>(bm, bn, tah, a2h, (void*)aB,  Cq, DA, a0, nullptr, nullptr); break;
        default: gemm_body<5,0>(bm, bn, tvh, v2h, (void*)vB, Cq, DV, v0, vB, vfirst);       break;
    }
}

// ---------------------------------------------------------------------------
// kk normalize + k transform
// ---------------------------------------------------------------------------
__global__ void kk_kernel(float* __restrict__ k, const float* __restrict__ a,
                          const float* __restrict__ k_k, const float* __restrict__ k_a,
                          float* __restrict__ kk)
{
    int gw   = blockIdx.x*8 + (threadIdx.x>>5);
    int lane = threadIdx.x & 31;
    int m = gw >> 5;
    int h = gw & 31;
    size_t base = (size_t)m*Cq + h*HSq;
    int c0 = h*HSq + lane, c1 = c0 + 32;
    float k0 = k[base+lane], k1 = k[base+lane+32];
    float kk0 = k0*k_k[c0], kk1 = k1*k_k[c1];
    float s = kk0*kk0 + kk1*kk1;
    #pragma unroll
    for (int off=16; off; off>>=1) s += __shfl_xor_sync(0xffffffffu, s, off);
    float inv = 1.0f / fmaxf(sqrtf(s), 1e-12f);
    kk[base+lane]    = kk0*inv;
    kk[base+lane+32] = kk1*inv;
    float a0 = a[base+lane], a1 = a[base+lane+32];
    k[base+lane]    = k0*(1.0f + (a0-1.0f)*k_a[c0]);
    k[base+lane+32] = k1*(1.0f + (a1-1.0f)*k_a[c1]);
}

// ---------------------------------------------------------------------------
// WKV7 scan body (128 threads): thread (i,p) = state row i, half p (32 cols)
// ---------------------------------------------------------------------------
__device__ __forceinline__
void wkv_body(int bh, int tid,
              const float* __restrict__ r, const float* __restrict__ wd,
              const float* __restrict__ k, const float* __restrict__ v,
              const float* __restrict__ kkp, const float* __restrict__ ap,
              float* __restrict__ y)
{
    const int b = bh >> 5, h = bh & 31;
    const int i = tid >> 1;
    const int p = tid & 1;
    const int role = tid >> 6;
    const int lc   = tid & 63;

    __shared__ __align__(16) float sbuf[2][6][64];

    float st[32];
    #pragma unroll
    for (int j=0;j<32;j++) st[j]=0.f;

    const size_t base = ((size_t)b*Tq)*Cq + (size_t)h*HSq;

    float l0, l1, l2;
    if (role==0){ l0 = r[base+lc];  l1 = v[base+lc];   l2 = wd[base+lc]; }
    else        { l0 = k[base+lc];  l1 = kkp[base+lc]; l2 = ap[base+lc]; }

    size_t o = base;
    for (int t=0; t<Tq; t++){
        const int cur = t&1;

        if (role==0){ sbuf[cur][0][lc]=l0; sbuf[cur][5][lc]=l1; sbuf[cur][1][lc]=l2; }
        else        { sbuf[cur][2][lc]=l0; sbuf[cur][3][lc]=-l1; sbuf[cur][4][lc]=l1*l2; }
        __syncthreads();

        if (t+1 < Tq){
            size_t on = o + Cq;
            if (role==0){ l0 = r[on+lc];  l1 = v[on+lc];   l2 = wd[on+lc]; }
            else        { l0 = k[on+lc];  l1 = kkp[on+lc]; l2 = ap[on+lc]; }
        }

        const float4* A4 = (const float4*)&sbuf[cur][3][p*32];
        float s0=0,s1=0,s2=0,s3=0;
        #pragma unroll
        for (int j=0;j<8;j++){
            float4 a4 = A4[j];
            s0 += st[4*j+0]*a4.x; s1 += st[4*j+1]*a4.y;
            s2 += st[4*j+2]*a4.z; s3 += st[4*j+3]*a4.w;
        }
        float sav = (s0+s1)+(s2+s3);
        sav += __shfl_xor_sync(0xffffffffu, sav, 1);

        const float vv = sbuf[cur][5][i];
        const float4* W4=(const float4*)&sbuf[cur][1][p*32];
        const float4* K4=(const float4*)&sbuf[cur][2][p*32];
        const float4* B4=(const float4*)&sbuf[cur][4][p*32];
        const float4* R4=(const float4*)&sbuf[cur][0][p*32];
        float o0=0,o1=0,o2=0,o3=0;
        #pragma unroll
        for (int j=0;j<8;j++){
            float4 w4=W4[j], k4=K4[j], b4=B4[j], r4=R4[j];
            float t0 = st[4*j+0]*w4.x + vv*k4.x + sav*b4.x;
            float t1 = st[4*j+1]*w4.y + vv*k4.y + sav*b4.y;
            float t2 = st[4*j+2]*w4.z + vv*k4.z + sav*b4.z;
            float t3 = st[4*j+3]*w4.w + vv*k4.w + sav*b4.w;
            st[4*j+0]=t0; st[4*j+1]=t1; st[4*j+2]=t2; st[4*j+3]=t3;
            o0 += t0*r4.x; o1 += t1*r4.y; o2 += t2*r4.z; o3 += t3*r4.w;
        }
        float op = (o0+o1)+(o2+o3);
        op += __shfl_xor_sync(0xffffffffu, op, 1);
        if (p==0) y[o+i] = op;

        o += Cq;
    }
}

// ---------------------------------------------------------------------------
// Merged launch: blocks 0-127 = WKV scan (threads>=128 exit); blocks 128+ =
// gate down-projection GEMM (overlaps with the scan's GPU under-utilization).
// ---------------------------------------------------------------------------
__global__ __launch_bounds__(256,2)
void wkv_gate(const float* __restrict__ r, const float* __restrict__ wd,
              const float* __restrict__ k, const float* __restrict__ v,
              const float* __restrict__ kkp, const float* __restrict__ ap,
              float* __restrict__ y,
              const __half* __restrict__ tgh, const __half* __restrict__ g2h,
              float* __restrict__ gB)
{
    if (blockIdx.x < 128){
        if (threadIdx.x >= 128) return;   // warps 4-7 exit entirely
        wkv_body(blockIdx.x, threadIdx.x, r, wd, k, v, kkp, ap, y);
        return;
    }
    int idx = blockIdx.x - 128;
    int bn = (idx & 15) * 128;            // Cq/128 = 16 n-tiles
    int bm = (idx >> 4) * 128;            // Mq/128 = 64 m-tiles
    gemm_body<0,0>(bm, bn, tgh, g2h, (void*)gB, Cq, DGp, nullptr, nullptr, nullptr);
}

// ---------------------------------------------------------------------------
// GroupNorm + bonus + gate -> z (fp16 for Wo gemm)
// ---------------------------------------------------------------------------
__global__ void gn_kernel(const float* __restrict__ y, const float* __restrict__ r,
                          const float* __restrict__ k, const float* __restrict__ v,
                          const float* __restrict__ g,
                          const float* __restrict__ lnw, const float* __restrict__ lnb,
                          const float* __restrict__ r_k, __half* __restrict__ z)
{
    int gw   = blockIdx.x*8 + (threadIdx.x>>5);
    int lane = threadIdx.x & 31;
    int m = gw >> 5;
    int h = gw & 31;
    size_t base = (size_t)m*Cq + h*HSq;
    int c0 = h*HSq + lane, c1 = c0 + 32;
    float y0=y[base+lane], y1=y[base+lane+32];
    float r0=r[base+lane], r1=r[base+lane+32];
    float k0=k[base+lane], k1=k[base+lane+32];
    float sum = y0+y1;
    float sq  = y0*y0 + y1*y1;
    float dot = r0*k0*r_k[c0] + r1*k1*r_k[c1];
    #pragma unroll
    for (int off=16; off; off>>=1) {
        sum += __shfl_xor_sync(0xffffffffu, sum, off);
        sq  += __shfl_xor_sync(0xffffffffu, sq , off);
        dot += __shfl_xor_sync(0xffffffffu, dot, off);
    }
    float mean = sum * (1.0f/64.0f);
    float var  = sq * (1.0f/64.0f) - mean*mean;
    float inv  = rsqrtf(var + EPS_GN);
    float v0=v[base+lane], v1=v[base+lane+32];
    float g0=g[base+lane], g1=g[base+lane+32];
    float z0 = ((y0-mean)*inv*lnw[c0] + lnb[c0] + dot*v0) * g0;
    float z1 = ((y1-mean)*inv*lnw[c1] + lnb[c1] + dot*v1) * g1;
    z[base+lane]    = __float2half_rn(z0);
    z[base+lane+32] = __float2half_rn(z1);
}

// ---------------------------------------------------------------------------
// Host helpers
// ---------------------------------------------------------------------------
#define SMEM_GEMM (GST*ST_BYTES)

template<int EPI,int RND>
static void rg(const __half* A, const __half* Bw, void* C, int Nd, int Kd,
               const float* bias, const float* vold, const float* vfirst)
{
    cudaFuncSetAttribute(gemm_h<EPI,RND>, cudaFuncAttributeMaxDynamicSharedMemorySize,
                         SMEM_GEMM);
    dim3 grid((Nd+127)/128, Mq/128);
    gemm_h<EPI,RND><<<grid, 256, SMEM_GEMM>>>(A, Bw, C, Nd, Kd, bias, vold, vfirst);
}

// ---------------------------------------------------------------------------
// Launch
// ---------------------------------------------------------------------------
extern "C" void kernel_launch(void* const* d_in, const int* in_sizes, int n_in,
                              void* d_out, int out_size)
{
    const float* x       = (const float*)d_in[0];
    const float* v_first = (const float*)d_in[1];
    const float* x_r = (const float*)d_in[2];
    const float* x_w = (const float*)d_in[3];
    const float* x_k = (const float*)d_in[4];
    const float* x_v = (const float*)d_in[5];
    const float* x_a = (const float*)d_in[6];
    const float* x_g = (const float*)d_in[7];
    const float* w0  = (const float*)d_in[8];
    const float* w1  = (const float*)d_in[9];
    const float* w2  = (const float*)d_in[10];
    const float* a0  = (const float*)d_in[11];
    const float* a1  = (const float*)d_in[12];
    const float* a2  = (const float*)d_in[13];
    const float* v0  = (const float*)d_in[14];
    const float* v1  = (const float*)d_in[15];
    const float* v2  = (const float*)d_in[16];
    const float* g1  = (const float*)d_in[17];
    const float* g2  = (const float*)d_in[18];
    const float* k_k = (const float*)d_in[19];
    const float* k_a = (const float*)d_in[20];
    const float* r_k = (const float*)d_in[21];
    const float* Wr  = (const float*)d_in[22];
    const float* Wk  = (const float*)d_in[23];
    const float* Wv  = (const float*)d_in[24];
    const float* Wo  = (const float*)d_in[25];
    const float* lnw = (const float*)d_in[26];
    const float* lnb = (const float*)d_in[27];
    float* out = (float*)d_out;

    __half *xr,*xw,*xk,*xv,*xa,*xg,*zh,*Wrh,*Wkh,*Wvh,*Woh;
    __half *w1h,*w2h,*a1h,*a2h,*v1h,*v2h,*g1h,*g2h,*twh,*tah,*tvh,*tgh;
    float *rB,*kB,*vB,*dec,*aB,*gB,*kkB,*yB;
    cudaGetSymbolAddress((void**)&xr , h_xr);
    cudaGetSymbolAddress((void**)&xw , h_xw);
    cudaGetSymbolAddress((void**)&xk , h_xk);
    cudaGetSymbolAddress((void**)&xv , h_xv);
    cudaGetSymbolAddress((void**)&xa , h_xa);
    cudaGetSymbolAddress((void**)&xg , h_xg);
    cudaGetSymbolAddress((void**)&zh , h_z);
    cudaGetSymbolAddress((void**)&Wrh, h_Wr);
    cudaGetSymbolAddress((void**)&Wkh, h_Wk);
    cudaGetSymbolAddress((void**)&Wvh, h_Wv);
    cudaGetSymbolAddress((void**)&Woh, h_Wo);
    cudaGetSymbolAddress((void**)&w1h, h_w1);
    cudaGetSymbolAddress((void**)&w2h, h_w2);
    cudaGetSymbolAddress((void**)&a1h, h_a1);
    cudaGetSymbolAddress((void**)&a2h, h_a2);
    cudaGetSymbolAddress((void**)&v1h, h_v1);
    cudaGetSymbolAddress((void**)&v2h, h_v2);
    cudaGetSymbolAddress((void**)&g1h, h_g1);
    cudaGetSymbolAddress((void**)&g2h, h_g2);
    cudaGetSymbolAddress((void**)&twh, h_tw);
    cudaGetSymbolAddress((void**)&tah, h_ta);
    cudaGetSymbolAddress((void**)&tvh, h_tv);
    cudaGetSymbolAddress((void**)&tgh, h_tg);
    cudaGetSymbolAddress((void**)&rB , g_r);
    cudaGetSymbolAddress((void**)&kB , g_k);
    cudaGetSymbolAddress((void**)&vB , g_v);
    cudaGetSymbolAddress((void**)&dec, g_dec);
    cudaGetSymbolAddress((void**)&aB , g_a);
    cudaGetSymbolAddress((void**)&gB , g_g);
    cudaGetSymbolAddress((void**)&kkB, g_kk);
    cudaGetSymbolAddress((void**)&yB , g_y);

    // big weights f32->f16 (one launch)
    f2h4_kernel<<<dim3((unsigned)(((size_t)Cq*Cq/4 + 255)/256), 4), 256>>>(
        Wr, Wrh, Wk, Wkh, Wv, Wvh, Wo, Woh, (size_t)Cq*Cq/4);

    // lora weight transposes (one launch; g2 padded to K-stride 256)
    transpose8b<<<dim3(64, 64, 8), dim3(32,8)>>>(w1, w1h, w2, w2h, a1, a1h, a2, a2h,
                                                 v1, v1h, v2, v2h, g1, g1h, g2, g2h);

    // token-shift mixes -> fp16 (2 float4 groups / thread)
    mix_kernel<<<(unsigned)((BTC/8 + 255)/256), 256>>>(x, x_r,x_w,x_k,x_v,x_a,x_g,
                                                       xr,xw,xk,xv,xa,xg);

    // merged big projections r/k/v (one launch)
    cudaFuncSetAttribute(gemm_h3, cudaFuncAttributeMaxDynamicSharedMemorySize, SMEM_GEMM);
    gemm_h3<<<dim3(Cq/128, Mq/128, 3), 256, SMEM_GEMM>>>(
        xr, Wrh, rB, xk, Wkh, kB, xv, Wvh, vB);

    // lora up-projections (one launch)
    cudaFuncSetAttribute(gemm_lora4, cudaFuncAttributeMaxDynamicSharedMemorySize, SMEM_GEMM);
    gemm_lora4<<<dim3(2, Mq/128, 4), 256, SMEM_GEMM>>>(
        xw, w1h, twh, xa, a1h, tah, xv, v1h, tvh, xg, g1h, tgh);

    // lora down-projections dec/a/v (one launch; gate deferred into wkv_gate)
    cudaFuncSetAttribute(gemm_lorad3, cudaFuncAttributeMaxDynamicSharedMemorySize, SMEM_GEMM);
    gemm_lorad3<<<dim3(Cq/128, Mq/128, 3), 256, SMEM_GEMM>>>(
        twh, w2h, dec, w0, tah, a2h, aB, a0, tvh, v2h, vB, v0, v_first);

    // kk normalize + k transform
    kk_kernel<<<Mq*Hq/8, 256>>>(kB, aB, k_k, k_a, kkB);

    // WKV7 scan + gate down-projection (merged, overlapped)
    cudaFuncSetAttribute(wkv_gate, cudaFuncAttributeMaxDynamicSharedMemorySize, SMEM_GEMM);
    wkv_gate<<<128 + (Cq/128)*(Mq/128), 256, SMEM_GEMM>>>(
        rB, dec, kB, vB, kkB, aB, yB, tgh, g2h, gB);

    // GroupNorm + bonus + gate -> fp16 z
    gn_kernel<<<Mq*Hq/8, 256>>>(yB, rB, kB, vB, gB, lnw, lnb, r_k, zh);

    // output projection
    rg<0,0>(zh, Woh, out, Cq, Cq, nullptr,nullptr,nullptr);
}

// round 14
// speedup vs baseline: 1.1293x; 1.1293x over previous
#include <cuda_runtime.h>
#include <cuda_fp16.h>
#include <math.h>
#include <stdint.h>

// Problem constants
#define Bq 4
#define Tq 2048
#define Cq 2048
#define Hq 32
#define HSq 64
#define Mq (Bq*Tq)            // 8192 tokens
#define DW 128
#define DA 128
#define DG 224
#define DGp 256               // padded K for g lora (BK=64 divisibility)
#define DV 64
#define EPS_GN 0.00064f

// ---------------------------------------------------------------------------
// Scratch (static device globals; zero-initialized at module load)
// ---------------------------------------------------------------------------
#define BTC ((size_t)Mq*Cq)
__device__ __half h_xr[BTC];
__device__ __half h_xw[BTC];
__device__ __half h_xk[BTC];
__device__ __half h_xv[BTC];
__device__ __half h_xa[BTC];
__device__ __half h_xg[BTC];
__device__ __half h_z [BTC];
__device__ __half h_Wr[(size_t)Cq*Cq];
__device__ __half h_Wk[(size_t)Cq*Cq];
__device__ __half h_Wv[(size_t)Cq*Cq];
__device__ __half h_Wo[(size_t)Cq*Cq];
__device__ __half h_w1[(size_t)128*Cq];
__device__ __half h_w2[(size_t)Cq*DW];
__device__ __half h_a1[(size_t)128*Cq];
__device__ __half h_a2[(size_t)Cq*DA];
__device__ __half h_v1[(size_t)128*Cq];
__device__ __half h_v2[(size_t)Cq*DV];
__device__ __half h_g1[(size_t)DGp*Cq];   // pad rows stay 0
__device__ __half h_g2[(size_t)Cq*DGp];   // pad cols stay 0
__device__ __half h_tw[(size_t)Mq*DW];
__device__ __half h_ta[(size_t)Mq*DA];
__device__ __half h_tv[(size_t)Mq*DV];
__device__ __half h_tg[(size_t)Mq*DGp];   // stride 256
// fp32 intermediates
__device__ float g_r [BTC];
__device__ float g_k [BTC];
__device__ float g_v [BTC];
__device__ float g_dec[BTC];
__device__ float g_a [BTC];
__device__ float g_g [BTC];
__device__ float g_kk[BTC];
__device__ float g_y [BTC];

__device__ __forceinline__ float sigmoidf_(float x){ return 1.0f/(1.0f+expf(-x)); }

__device__ __forceinline__ void cpa16(uint32_t s, const void* g){
    asm volatile("cp.async.cg.shared.global [%0], [%1], 16;\n" :: "r"(s), "l"(g));
}
__device__ __forceinline__ void ldsm_x4(uint32_t* r, uint32_t addr){
    asm volatile("ldmatrix.sync.aligned.m8n8.x4.shared.b16 {%0,%1,%2,%3}, [%4];"
        : "=r"(r[0]),"=r"(r[1]),"=r"(r[2]),"=r"(r[3]) : "r"(addr));
}
__device__ __forceinline__ void mma16(float* c, const uint32_t* a, const uint32_t* b){
    asm volatile("mma.sync.aligned.m16n8k16.row.col.f32.f16.f16.f32 "
        "{%0,%1,%2,%3},{%4,%5,%6,%7},{%8,%9},{%0,%1,%2,%3};\n"
        : "+f"(c[0]),"+f"(c[1]),"+f"(c[2]),"+f"(c[3])
        : "r"(a[0]),"r"(a[1]),"r"(a[2]),"r"(a[3]),"r"(b[0]),"r"(b[1]));
}

// ---------------------------------------------------------------------------
// Prep: 4x f32->f16 weight copies in ONE launch (blockIdx.y selects)
// ---------------------------------------------------------------------------
__global__ void f2h4_kernel(const float* __restrict__ i0, __half* __restrict__ o0,
                            const float* __restrict__ i1, __half* __restrict__ o1,
                            const float* __restrict__ i2, __half* __restrict__ o2,
                            const float* __restrict__ i3, __half* __restrict__ o3,
                            size_t n4)
{
    size_t i = (size_t)blockIdx.x*blockDim.x + threadIdx.x;
    if (i >= n4) return;
    const float* in = (blockIdx.y==0)?i0:(blockIdx.y==1)?i1:(blockIdx.y==2)?i2:i3;
    __half* out     = (blockIdx.y==0)?o0:(blockIdx.y==1)?o1:(blockIdx.y==2)?o2:o3;
    float4 v = ((const float4*)in)[i];
    ((__half2*)out)[i*2  ] = __floats2half2_rn(v.x, v.y);
    ((__half2*)out)[i*2+1] = __floats2half2_rn(v.z, v.w);
}

// ---------------------------------------------------------------------------
// 8 lora-weight transposes in ONE launch; out[c2*Rs + r2]
// ---------------------------------------------------------------------------
__device__ __forceinline__
void transpose_body(const float* __restrict__ in, __half* __restrict__ out,
                    int R, int C, int Rs)
{
    __shared__ float tile[32][33];
    int cb = blockIdx.x*32, rb = blockIdx.y*32;
    if (cb >= C || rb >= R) return;
    int c = cb + threadIdx.x;
    #pragma unroll
    for (int i=threadIdx.y; i<32; i+=8){
        int r = rb + i;
        if (r<R && c<C) tile[i][threadIdx.x] = in[(size_t)r*C + c];
    }
    __syncthreads();
    int r2 = rb + threadIdx.x;
    #pragma unroll
    for (int i=threadIdx.y; i<32; i+=8){
        int c2 = cb + i;
        if (r2<R && c2<C) out[(size_t)c2*Rs + r2] = __float2half_rn(tile[threadIdx.x][i]);
    }
}

__global__ void transpose8b(const float* w1, __half* w1h, const float* w2, __half* w2h,
                            const float* a1, __half* a1h, const float* a2, __half* a2h,
                            const float* v1, __half* v1h, const float* v2, __half* v2h,
                            const float* g1, __half* g1h, const float* g2, __half* g2h)
{
    switch(blockIdx.z){
        case 0: transpose_body(w1, w1h, Cq, DW, Cq);  break;
        case 1: transpose_body(w2, w2h, DW, Cq, DW);  break;
        case 2: transpose_body(a1, a1h, Cq, DA, Cq);  break;
        case 3: transpose_body(a2, a2h, DA, Cq, DA);  break;
        case 4: transpose_body(v1, v1h, Cq, DV, Cq);  break;
        case 5: transpose_body(v2, v2h, DV, Cq, DV);  break;
        case 6: transpose_body(g1, g1h, Cq, DG, Cq);  break;
        default: transpose_body(g2, g2h, DG, Cq, DGp); break;
    }
}

// ---------------------------------------------------------------------------
// Token-shift mix -> fp16; 2 independent float4 groups per thread (MLP=4)
// ---------------------------------------------------------------------------
__global__ void mix_kernel(const float* __restrict__ x,
                           const float* __restrict__ cr, const float* __restrict__ cw,
                           const float* __restrict__ ck, const float* __restrict__ cv,
                           const float* __restrict__ ca, const float* __restrict__ cg,
                           __half* __restrict__ xr, __half* __restrict__ xw,
                           __half* __restrict__ xk, __half* __restrict__ xv,
                           __half* __restrict__ xa, __half* __restrict__ xg)
{
    size_t i8 = (size_t)blockIdx.x*blockDim.x + threadIdx.x;   // 8-float group
    size_t n8 = BTC/8;
    if (i8 >= n8) return;
    size_t i4a = i8*2, i4b = i8*2 + 1;       // same token row (8 | 2048)
    int tok = (int)((i4a*4) / Cq);
    int t   = tok % Tq;
    const float4* x4 = (const float4*)x;
    float4 xc0 = x4[i4a], xc1 = x4[i4b];
    float4 xp0, xp1;
    if (t==0){ xp0 = make_float4(0,0,0,0); xp1 = make_float4(0,0,0,0); }
    else     { xp0 = x4[i4a - Cq/4]; xp1 = x4[i4b - Cq/4]; }
    float4 dx0 = make_float4(xp0.x-xc0.x, xp0.y-xc0.y, xp0.z-xc0.z, xp0.w-xc0.w);
    float4 dx1 = make_float4(xp1.x-xc1.x, xp1.y-xc1.y, xp1.z-xc1.z, xp1.w-xc1.w);
    size_t c4a = i4a % (Cq/4), c4b = i4b % (Cq/4);
    #define MIX1(COEF, OUT) { \
        float4 cf0 = ((const float4*)COEF)[c4a]; \
        float4 cf1 = ((const float4*)COEF)[c4b]; \
        ((__half2*)OUT)[i4a*2  ] = __floats2half2_rn(xc0.x + dx0.x*cf0.x, xc0.y + dx0.y*cf0.y); \
        ((__half2*)OUT)[i4a*2+1] = __floats2half2_rn(xc0.z + dx0.z*cf0.z, xc0.w + dx0.w*cf0.w); \
        ((__half2*)OUT)[i4b*2  ] = __floats2half2_rn(xc1.x + dx1.x*cf1.x, xc1.y + dx1.y*cf1.y); \
        ((__half2*)OUT)[i4b*2+1] = __floats2half2_rn(xc1.z + dx1.z*cf1.z, xc1.w + dx1.w*cf1.w); }
    MIX1(cr, xr) MIX1(cw, xw) MIX1(ck, xk) MIX1(cv, xv) MIX1(ca, xa) MIX1(cg, xg)
    #undef MIX1
}

// ---------------------------------------------------------------------------
// Epilogue transform: 0 none, 1 tanh, 2 sigmoid, 3 w->decay, 4 a-sigm, 5 v-mix
// ---------------------------------------------------------------------------
template<int EPI>
__device__ __forceinline__ float epi_val(float val, int m, int n, int Nd,
                                         const float* __restrict__ bias,
                                         const float* __restrict__ vold,
                                         const float* __restrict__ vfirst)
{
    if (EPI==1) { val = tanhf(val); }
    else if (EPI==2) { val = sigmoidf_(val); }
    else if (EPI==3) {
        float w = bias[n] + val;
        float mneg = -w;
        float sp = fmaxf(mneg,0.f) + log1pf(expf(-fabsf(mneg)));
        float wl = -sp - 0.5f;
        val = expf(-expf(wl));
    }
    else if (EPI==4) { val = sigmoidf_(bias[n] + val); }
    else if (EPI==5) {
        float s  = sigmoidf_(bias[n] + val);
        size_t idx = (size_t)m*Nd + n;
        float vo = vold[idx];
        val = vo + (vfirst[idx] - vo)*s;
    }
    return val;
}

// ---------------------------------------------------------------------------
// fp16 tensor-core GEMM body: C[m,n] = sum_k A[m,k] * B[n,k]
// CTA 128x128, BK=64, 3-stage cp.async ring, ONE __syncthreads per slab.
// ---------------------------------------------------------------------------
#define GST 3
#define ST_HB (128*72*2)
#define ST_BYTES (2*ST_HB)

template<int EPI,int RND>
__device__ __forceinline__
void gemm_body(const __half* __restrict__ A, const __half* __restrict__ Bw,
               void* __restrict__ Cm, int Nd, int Kd,
               const float* __restrict__ bias,
               const float* __restrict__ vold, const float* __restrict__ vfirst)
{
    extern __shared__ __align__(128) char smc[];
    const int tid = threadIdx.x;
    const int lane = tid&31, warp = tid>>5;
    const int bm = blockIdx.y*128, bn = blockIdx.x*128;
    const int wm = (warp&1)*64, wn = (warp>>1)*32;
    const int g = lane>>2, tig = lane&3;
    const uint32_t sbase = (uint32_t)__cvta_generic_to_shared(smc);

    const int arow = wm + (lane&7) + ((lane>>3)&1)*8;
    const int akof = (lane>>4)*8;
    const int brow = wn + (lane&7) + (lane>>4)*8;
    const int bkof = ((lane>>3)&1)*8;

    float acc[4][4][4];
    #pragma unroll
    for (int i=0;i<4;i++)
        #pragma unroll
        for (int j=0;j<4;j++)
            #pragma unroll
            for (int q=0;q<4;q++) acc[i][j][q]=0.f;

    const int NS = Kd >> 6;

    auto loadSlab = [&](int s, int st){
        const uint32_t sb = sbase + st*ST_BYTES;
        const int k0 = s*64;
        #pragma unroll
        for (int i=0;i<4;i++){
            int id  = tid + i*256;
            int row = id>>3, c16 = id&7;
            cpa16(sb + row*144 + c16*16,
                  &A[(size_t)(bm+row)*Kd + k0 + c16*8]);
            cpa16(sb + ST_HB + row*144 + c16*16,
                  &Bw[(size_t)(bn+row)*Kd + k0 + c16*8]);
        }
    };
    auto compute = [&](int st){
        const uint32_t sb = sbase + st*ST_BYTES;
        #pragma unroll
        for (int ks=0; ks<4; ks++){
            uint32_t af[4][4], bf[2][4];
            #pragma unroll
            for (int mt=0;mt<4;mt++)
                ldsm_x4(af[mt], sb + ((arow+mt*16)*72 + akof + ks*16)*2);
            #pragma unroll
            for (int p=0;p<2;p++)
                ldsm_x4(bf[p], sb + ST_HB + ((brow+p*16)*72 + bkof + ks*16)*2);
            #pragma unroll
            for (int mt=0;mt<4;mt++)
                #pragma unroll
                for (int nt=0;nt<4;nt++)
                    mma16(acc[mt][nt], af[mt], &bf[nt>>1][(nt&1)*2]);
        }
    };

    #pragma unroll
    for (int i=0;i<GST-1;i++){
        if (i<NS) loadSlab(i,i);
        asm volatile("cp.async.commit_group;\n");
    }
    int st = 0;
    for (int s=0;s<NS;s++){
        asm volatile("cp.async.wait_group %0;\n" :: "n"(GST-2));
        __syncthreads();
        int ld = s + GST-1;
        if (ld < NS){
            int lst = st + 2; if (lst >= 3) lst -= 3;
            loadSlab(ld, lst);
        }
        asm volatile("cp.async.commit_group;\n");
        compute(st);
        if (++st == 3) st = 0;
    }

    #pragma unroll
    for (int mt=0;mt<4;mt++){
        int r0 = bm + wm + mt*16 + g;
        #pragma unroll
        for (int nt=0;nt<4;nt++){
            int n0 = bn + wn + nt*8 + tig*2;
            if (n0 < Nd){
                float* c = acc[mt][nt];
                float v00 = epi_val<EPI>(c[0], r0,   n0,   Nd, bias, vold, vfirst);
                float v01 = epi_val<EPI>(c[1], r0,   n0+1, Nd, bias, vold, vfirst);
                float v10 = epi_val<EPI>(c[2], r0+8, n0,   Nd, bias, vold, vfirst);
                float v11 = epi_val<EPI>(c[3], r0+8, n0+1, Nd, bias, vold, vfirst);
                if (RND){
                    __half* O = (__half*)Cm;
                    *(__half2*)&O[(size_t)r0*Nd + n0]     = __floats2half2_rn(v00, v01);
                    *(__half2*)&O[(size_t)(r0+8)*Nd + n0] = __floats2half2_rn(v10, v11);
                } else {
                    float* O = (float*)Cm;
                    *(float2*)&O[(size_t)r0*Nd + n0]     = make_float2(v00, v01);
                    *(float2*)&O[(size_t)(r0+8)*Nd + n0] = make_float2(v10, v11);
                }
            }
        }
    }
}

template<int EPI,int RND>
__global__ __launch_bounds__(256,2)
void gemm_h(const __half* __restrict__ A, const __half* __restrict__ Bw,
            void* __restrict__ Cm, int Nd, int Kd,
            const float* __restrict__ bias,
            const float* __restrict__ vold, const float* __restrict__ vfirst)
{
    gemm_body<EPI,RND>(A, Bw, Cm, Nd, Kd, bias, vold, vfirst);
}

// merged r/k/v projections
__global__ __launch_bounds__(256,2)
void gemm_h3(const __half* __restrict__ A0, const __half* __restrict__ B0, float* __restrict__ C0,
             const __half* __restrict__ A1, const __half* __restrict__ B1, float* __restrict__ C1,
             const __half* __restrict__ A2, const __half* __restrict__ B2, float* __restrict__ C2)
{
    const __half* A = (blockIdx.z==0) ? A0 : (blockIdx.z==1) ? A1 : A2;
    const __half* B = (blockIdx.z==0) ? B0 : (blockIdx.z==1) ? B1 : B2;
    float*        C = (blockIdx.z==0) ? C0 : (blockIdx.z==1) ? C1 : C2;
    gemm_body<0,0>(A, B, (void*)C, Cq, Cq, nullptr, nullptr, nullptr);
}

// 4 lora up-projections in ONE launch
__global__ __launch_bounds__(256,2)
void gemm_lora4(const __half* __restrict__ xw, const __half* __restrict__ w1h, __half* __restrict__ tw,
                const __half* __restrict__ xa, const __half* __restrict__ a1h, __half* __restrict__ ta,
                const __half* __restrict__ xv, const __half* __restrict__ v1h, __half* __restrict__ tv,
                const __half* __restrict__ xg, const __half* __restrict__ g1h, __half* __restrict__ tg)
{
    const int bn = blockIdx.x*128;
    switch(blockIdx.z){
        case 0: if (bn >= DW) return; gemm_body<1,1>(xw, w1h, (void*)tw, DW,  Cq, nullptr,nullptr,nullptr); break;
        case 1: if (bn >= DA) return; gemm_body<0,1>(xa, a1h, (void*)ta, DA,  Cq, nullptr,nullptr,nullptr); break;
        case 2: if (bn >= DV) return; gemm_body<0,1>(xv, v1h, (void*)tv, DV,  Cq, nullptr,nullptr,nullptr); break;
        default:                      gemm_body<2,1>(xg, g1h, (void*)tg, DGp, Cq, nullptr,nullptr,nullptr); break;
    }
}

// 4 lora down-projections in ONE launch
__global__ __launch_bounds__(256,2)
void gemm_lorad4(const __half* __restrict__ twh, const __half* __restrict__ w2h, float* __restrict__ dec, const float* __restrict__ w0,
                 const __half* __restrict__ tah, const __half* __restrict__ a2h, float* __restrict__ aB,  const float* __restrict__ a0,
                 const __half* __restrict__ tvh, const __half* __restrict__ v2h, float* __restrict__ vB,  const float* __restrict__ v0,
                 const float* __restrict__ vfirst,
                 const __half* __restrict__ tgh, const __half* __restrict__ g2h, float* __restrict__ gB)
{
    switch(blockIdx.z){
        case 0: gemm_body<3,0>(twh, w2h, (void*)dec, Cq, DW, w0, nullptr, nullptr); break;
        case 1: gemm_body<4,0>(tah, a2h, (void*)aB,  Cq, DA, a0, nullptr, nullptr); break;
        case 2: gemm_body<5,0>(tvh, v2h, (void*)vB,  Cq, DV, v0, vB, vfirst);       break;
        default: gemm_body<0,0>(tgh, g2h, (void*)gB, Cq, DGp, nullptr, nullptr, nullptr); break;
    }
}

// ---------------------------------------------------------------------------
// kk normalize + k transform
// ---------------------------------------------------------------------------
__global__ void kk_kernel(float* __restrict__ k, const float* __restrict__ a,
                          const float* __restrict__ k_k, const float* __restrict__ k_a,
                          float* __restrict__ kk)
{
    int gw   = blockIdx.x*8 + (threadIdx.x>>5);
    int lane = threadIdx.x & 31;
    int m = gw >> 5;
    int h = gw & 31;
    size_t base = (size_t)m*Cq + h*HSq;
    int c0 = h*HSq + lane, c1 = c0 + 32;
    float k0 = k[base+lane], k1 = k[base+lane+32];
    float kk0 = k0*k_k[c0], kk1 = k1*k_k[c1];
    float s = kk0*kk0 + kk1*kk1;
    #pragma unroll
    for (int off=16; off; off>>=1) s += __shfl_xor_sync(0xffffffffu, s, off);
    float inv = 1.0f / fmaxf(sqrtf(s), 1e-12f);
    kk[base+lane]    = kk0*inv;
    kk[base+lane+32] = kk1*inv;
    float a0 = a[base+lane], a1 = a[base+lane+32];
    k[base+lane]    = k0*(1.0f + (a0-1.0f)*k_a[c0]);
    k[base+lane+32] = k1*(1.0f + (a1-1.0f)*k_a[c1]);
}

// ---------------------------------------------------------------------------
// WKV7 scan: 128 threads per (b,h). Thread (i,p) owns state row i (0..63),
// half p (32 cols). Own launch — scan SMs stay exclusive (R13 lesson).
// ---------------------------------------------------------------------------
__global__ __launch_bounds__(128)
void wkv_kernel(const float* __restrict__ r, const float* __restrict__ wd,
                const float* __restrict__ k, const float* __restrict__ v,
                const float* __restrict__ kkp, const float* __restrict__ ap,
                float* __restrict__ y)
{
    const int bh = blockIdx.x;
    const int b = bh >> 5, h = bh & 31;
    const int tid = threadIdx.x;
    const int i = tid >> 1;
    const int p = tid & 1;
    const int role = tid >> 6;
    const int lc   = tid & 63;

    __shared__ __align__(16) float sbuf[2][6][64];

    float st[32];
    #pragma unroll
    for (int j=0;j<32;j++) st[j]=0.f;

    const size_t base = ((size_t)b*Tq)*Cq + (size_t)h*HSq;

    float l0, l1, l2;
    if (role==0){ l0 = r[base+lc];  l1 = v[base+lc];   l2 = wd[base+lc]; }
    else        { l0 = k[base+lc];  l1 = kkp[base+lc]; l2 = ap[base+lc]; }

    size_t o = base;
    for (int t=0; t<Tq; t++){
        const int cur = t&1;

        if (role==0){ sbuf[cur][0][lc]=l0; sbuf[cur][5][lc]=l1; sbuf[cur][1][lc]=l2; }
        else        { sbuf[cur][2][lc]=l0; sbuf[cur][3][lc]=-l1; sbuf[cur][4][lc]=l1*l2; }
        __syncthreads();

        if (t+1 < Tq){
            size_t on = o + Cq;
            if (role==0){ l0 = r[on+lc];  l1 = v[on+lc];   l2 = wd[on+lc]; }
            else        { l0 = k[on+lc];  l1 = kkp[on+lc]; l2 = ap[on+lc]; }
        }

        const float4* A4 = (const float4*)&sbuf[cur][3][p*32];
        float s0=0,s1=0,s2=0,s3=0;
        #pragma unroll
        for (int j=0;j<8;j++){
            float4 a4 = A4[j];
            s0 += st[4*j+0]*a4.x; s1 += st[4*j+1]*a4.y;
            s2 += st[4*j+2]*a4.z; s3 += st[4*j+3]*a4.w;
        }
        float sav = (s0+s1)+(s2+s3);
        sav += __shfl_xor_sync(0xffffffffu, sav, 1);

        const float vv = sbuf[cur][5][i];
        const float4* W4=(const float4*)&sbuf[cur][1][p*32];
        const float4* K4=(const float4*)&sbuf[cur][2][p*32];
        const float4* B4=(const float4*)&sbuf[cur][4][p*32];
        const float4* R4=(const float4*)&sbuf[cur][0][p*32];
        float o0=0,o1=0,o2=0,o3=0;
        #pragma unroll
        for (int j=0;j<8;j++){
            float4 w4=W4[j], k4=K4[j], b4=B4[j], r4=R4[j];
            float t0 = st[4*j+0]*w4.x + vv*k4.x + sav*b4.x;
            float t1 = st[4*j+1]*w4.y + vv*k4.y + sav*b4.y;
            float t2 = st[4*j+2]*w4.z + vv*k4.z + sav*b4.z;
            float t3 = st[4*j+3]*w4.w + vv*k4.w + sav*b4.w;
            st[4*j+0]=t0; st[4*j+1]=t1; st[4*j+2]=t2; st[4*j+3]=t3;
            o0 += t0*r4.x; o1 += t1*r4.y; o2 += t2*r4.z; o3 += t3*r4.w;
        }
        float op = (o0+o1)+(o2+o3);
        op += __shfl_xor_sync(0xffffffffu, op, 1);
        if (p==0) y[o+i] = op;

        o += Cq;
    }
}

// ---------------------------------------------------------------------------
// GroupNorm + bonus + gate -> z (fp16 for Wo gemm)
// ---------------------------------------------------------------------------
__global__ void gn_kernel(const float* __restrict__ y, const float* __restrict__ r,
                          const float* __restrict__ k, const float* __restrict__ v,
                          const float* __restrict__ g,
                          const float* __restrict__ lnw, const float* __restrict__ lnb,
                          const float* __restrict__ r_k, __half* __restrict__ z)
{
    int gw   = blockIdx.x*8 + (threadIdx.x>>5);
    int lane = threadIdx.x & 31;
    int m = gw >> 5;
    int h = gw & 31;
    size_t base = (size_t)m*Cq + h*HSq;
    int c0 = h*HSq + lane, c1 = c0 + 32;
    float y0=y[base+lane], y1=y[base+lane+32];
    float r0=r[base+lane], r1=r[base+lane+32];
    float k0=k[base+lane], k1=k[base+lane+32];
    float sum = y0+y1;
    float sq  = y0*y0 + y1*y1;
    float dot = r0*k0*r_k[c0] + r1*k1*r_k[c1];
    #pragma unroll
    for (int off=16; off; off>>=1) {
        sum += __shfl_xor_sync(0xffffffffu, sum, off);
        sq  += __shfl_xor_sync(0xffffffffu, sq , off);
        dot += __shfl_xor_sync(0xffffffffu, dot, off);
    }
    float mean = sum * (1.0f/64.0f);
    float var  = sq * (1.0f/64.0f) - mean*mean;
    float inv  = rsqrtf(var + EPS_GN);
    float v0=v[base+lane], v1=v[base+lane+32];
    float g0=g[base+lane], g1=g[base+lane+32];
    float z0 = ((y0-mean)*inv*lnw[c0] + lnb[c0] + dot*v0) * g0;
    float z1 = ((y1-mean)*inv*lnw[c1] + lnb[c1] + dot*v1) * g1;
    z[base+lane]    = __float2half_rn(z0);
    z[base+lane+32] = __float2half_rn(z1);
}

// ---------------------------------------------------------------------------
// Host helpers
// ---------------------------------------------------------------------------
#define SMEM_GEMM (GST*ST_BYTES)

template<int EPI,int RND>
static void rg(const __half* A, const __half* Bw, void* C, int Nd, int Kd,
               const float* bias, const float* vold, const float* vfirst)
{
    cudaFuncSetAttribute(gemm_h<EPI,RND>, cudaFuncAttributeMaxDynamicSharedMemorySize,
                         SMEM_GEMM);
    dim3 grid((Nd+127)/128, Mq/128);
    gemm_h<EPI,RND><<<grid, 256, SMEM_GEMM>>>(A, Bw, C, Nd, Kd, bias, vold, vfirst);
}

// ---------------------------------------------------------------------------
// Launch
// ---------------------------------------------------------------------------
extern "C" void kernel_launch(void* const* d_in, const int* in_sizes, int n_in,
                              void* d_out, int out_size)
{
    const float* x       = (const float*)d_in[0];
    const float* v_first = (const float*)d_in[1];
    const float* x_r = (const float*)d_in[2];
    const float* x_w = (const float*)d_in[3];
    const float* x_k = (const float*)d_in[4];
    const float* x_v = (const float*)d_in[5];
    const float* x_a = (const float*)d_in[6];
    const float* x_g = (const float*)d_in[7];
    const float* w0  = (const float*)d_in[8];
    const float* w1  = (const float*)d_in[9];
    const float* w2  = (const float*)d_in[10];
    const float* a0  = (const float*)d_in[11];
    const float* a1  = (const float*)d_in[12];
    const float* a2  = (const float*)d_in[13];
    const float* v0  = (const float*)d_in[14];
    const float* v1  = (const float*)d_in[15];
    const float* v2  = (const float*)d_in[16];
    const float* g1  = (const float*)d_in[17];
    const float* g2  = (const float*)d_in[18];
    const float* k_k = (const float*)d_in[19];
    const float* k_a = (const float*)d_in[20];
    const float* r_k = (const float*)d_in[21];
    const float* Wr  = (const float*)d_in[22];
    const float* Wk  = (const float*)d_in[23];
    const float* Wv  = (const float*)d_in[24];
    const float* Wo  = (const float*)d_in[25];
    const float* lnw = (const float*)d_in[26];
    const float* lnb = (const float*)d_in[27];
    float* out = (float*)d_out;

    __half *xr,*xw,*xk,*xv,*xa,*xg,*zh,*Wrh,*Wkh,*Wvh,*Woh;
    __half *w1h,*w2h,*a1h,*a2h,*v1h,*v2h,*g1h,*g2h,*twh,*tah,*tvh,*tgh;
    float *rB,*kB,*vB,*dec,*aB,*gB,*kkB,*yB;
    cudaGetSymbolAddress((void**)&xr , h_xr);
    cudaGetSymbolAddress((void**)&xw , h_xw);
    cudaGetSymbolAddress((void**)&xk , h_xk);
    cudaGetSymbolAddress((void**)&xv , h_xv);
    cudaGetSymbolAddress((void**)&xa , h_xa);
    cudaGetSymbolAddress((void**)&xg , h_xg);
    cudaGetSymbolAddress((void**)&zh , h_z);
    cudaGetSymbolAddress((void**)&Wrh, h_Wr);
    cudaGetSymbolAddress((void**)&Wkh, h_Wk);
    cudaGetSymbolAddress((void**)&Wvh, h_Wv);
    cudaGetSymbolAddress((void**)&Woh, h_Wo);
    cudaGetSymbolAddress((void**)&w1h, h_w1);
    cudaGetSymbolAddress((void**)&w2h, h_w2);
    cudaGetSymbolAddress((void**)&a1h, h_a1);
    cudaGetSymbolAddress((void**)&a2h, h_a2);
    cudaGetSymbolAddress((void**)&v1h, h_v1);
    cudaGetSymbolAddress((void**)&v2h, h_v2);
    cudaGetSymbolAddress((void**)&g1h, h_g1);
    cudaGetSymbolAddress((void**)&g2h, h_g2);
    cudaGetSymbolAddress((void**)&twh, h_tw);
    cudaGetSymbolAddress((void**)&tah, h_ta);
    cudaGetSymbolAddress((void**)&tvh, h_tv);
    cudaGetSymbolAddress((void**)&tgh, h_tg);
    cudaGetSymbolAddress((void**)&rB , g_r);
    cudaGetSymbolAddress((void**)&kB , g_k);
    cudaGetSymbolAddress((void**)&vB , g_v);
    cudaGetSymbolAddress((void**)&dec, g_dec);
    cudaGetSymbolAddress((void**)&aB , g_a);
    cudaGetSymbolAddress((void**)&gB , g_g);
    cudaGetSymbolAddress((void**)&kkB, g_kk);
    cudaGetSymbolAddress((void**)&yB , g_y);

    // big weights f32->f16 (one launch)
    f2h4_kernel<<<dim3((unsigned)(((size_t)Cq*Cq/4 + 255)/256), 4), 256>>>(
        Wr, Wrh, Wk, Wkh, Wv, Wvh, Wo, Woh, (size_t)Cq*Cq/4);

    // lora weight transposes (one launch; g2 padded to K-stride 256)
    transpose8b<<<dim3(64, 64, 8), dim3(32,8)>>>(w1, w1h, w2, w2h, a1, a1h, a2, a2h,
                                                 v1, v1h, v2, v2h, g1, g1h, g2, g2h);

    // token-shift mixes -> fp16 (2 float4 groups / thread)
    mix_kernel<<<(unsigned)((BTC/8 + 255)/256), 256>>>(x, x_r,x_w,x_k,x_v,x_a,x_g,
                                                       xr,xw,xk,xv,xa,xg);

    // merged big projections r/k/v (one launch)
    cudaFuncSetAttribute(gemm_h3, cudaFuncAttributeMaxDynamicSharedMemorySize, SMEM_GEMM);
    gemm_h3<<<dim3(Cq/128, Mq/128, 3), 256, SMEM_GEMM>>>(
        xr, Wrh, rB, xk, Wkh, kB, xv, Wvh, vB);

    // lora up-projections (one launch)
    cudaFuncSetAttribute(gemm_lora4, cudaFuncAttributeMaxDynamicSharedMemorySize, SMEM_GEMM);
    gemm_lora4<<<dim3(2, Mq/128, 4), 256, SMEM_GEMM>>>(
        xw, w1h, twh, xa, a1h, tah, xv, v1h, tvh, xg, g1h, tgh);

    // lora down-projections (one launch; g uses padded K=256)
    cudaFuncSetAttribute(gemm_lorad4, cudaFuncAttributeMaxDynamicSharedMemorySize, SMEM_GEMM);
    gemm_lorad4<<<dim3(Cq/128, Mq/128, 4), 256, SMEM_GEMM>>>(
        twh, w2h, dec, w0, tah, a2h, aB, a0, tvh, v2h, vB, v0, v_first, tgh, g2h, gB);

    // kk normalize + k transform
    kk_kernel<<<Mq*Hq/8, 256>>>(kB, aB, k_k, k_a, kkB);

    // WKV7 scan (own launch; scan SMs exclusive)
    wkv_kernel<<<Bq*Hq, 128>>>(rB, dec, kB, vB, kkB, aB, yB);

    // GroupNorm + bonus + gate -> fp16 z
    gn_kernel<<<Mq*Hq/8, 256>>>(yB, rB, kB, vB, gB, lnw, lnb, r_k, zh);

    // output projection
    rg<0,0>(zh, Woh, out, Cq, Cq, nullptr,nullptr,nullptr);
}

// round 15
// speedup vs baseline: 1.1525x; 1.0206x over previous
#include <cuda_runtime.h>
#include <cuda_fp16.h>
#include <math.h>
#include <stdint.h>

// Problem constants
#define Bq 4
#define Tq 2048
#define Cq 2048
#define Hq 32
#define HSq 64
#define Mq (Bq*Tq)            // 8192 tokens
#define DW 128
#define DA 128
#define DG 224
#define DGp 256               // padded K for g lora (BK=64 divisibility)
#define DV 64
#define EPS_GN 0.00064f

// ---------------------------------------------------------------------------
// Scratch (static device globals; zero-initialized at module load)
// ---------------------------------------------------------------------------
#define BTC ((size_t)Mq*Cq)
__device__ __half h_xr[BTC];
__device__ __half h_xw[BTC];
__device__ __half h_xk[BTC];
__device__ __half h_xv[BTC];
__device__ __half h_xa[BTC];
__device__ __half h_xg[BTC];
__device__ __half h_z [BTC];
__device__ __half h_Wr[(size_t)Cq*Cq];
__device__ __half h_Wk[(size_t)Cq*Cq];
__device__ __half h_Wv[(size_t)Cq*Cq];
__device__ __half h_Wo[(size_t)Cq*Cq];
__device__ __half h_w1[(size_t)128*Cq];
__device__ __half h_w2[(size_t)Cq*DW];
__device__ __half h_a1[(size_t)128*Cq];
__device__ __half h_a2[(size_t)Cq*DA];
__device__ __half h_v1[(size_t)128*Cq];
__device__ __half h_v2[(size_t)Cq*DV];
__device__ __half h_g1[(size_t)DGp*Cq];   // pad rows stay 0
__device__ __half h_g2[(size_t)Cq*DGp];   // pad cols stay 0
__device__ __half h_tw[(size_t)Mq*DW];
__device__ __half h_ta[(size_t)Mq*DA];
__device__ __half h_tv[(size_t)Mq*DV];
__device__ __half h_tg[(size_t)Mq*DGp];   // stride 256
// fp32 intermediates
__device__ float g_r [BTC];
__device__ float g_k [BTC];
__device__ float g_v [BTC];
__device__ float g_dec[BTC];
__device__ float g_a [BTC];
__device__ float g_g [BTC];
__device__ float g_kk[BTC];
__device__ float g_y [BTC];

__device__ __forceinline__ float sigmoidf_(float x){ return 1.0f/(1.0f+expf(-x)); }

__device__ __forceinline__ void cpa16(uint32_t s, const void* g){
    asm volatile("cp.async.cg.shared.global [%0], [%1], 16;\n" :: "r"(s), "l"(g));
}
__device__ __forceinline__ void ldsm_x4(uint32_t* r, uint32_t addr){
    asm volatile("ldmatrix.sync.aligned.m8n8.x4.shared.b16 {%0,%1,%2,%3}, [%4];"
        : "=r"(r[0]),"=r"(r[1]),"=r"(r[2]),"=r"(r[3]) : "r"(addr));
}
__device__ __forceinline__ void mma16(float* c, const uint32_t* a, const uint32_t* b){
    asm volatile("mma.sync.aligned.m16n8k16.row.col.f32.f16.f16.f32 "
        "{%0,%1,%2,%3},{%4,%5,%6,%7},{%8,%9},{%0,%1,%2,%3};\n"
        : "+f"(c[0]),"+f"(c[1]),"+f"(c[2]),"+f"(c[3])
        : "r"(a[0]),"r"(a[1]),"r"(a[2]),"r"(a[3]),"r"(b[0]),"r"(b[1]));
}

// ---------------------------------------------------------------------------
// Prep: 4x f32->f16 weight copies in ONE launch (blockIdx.y selects)
// ---------------------------------------------------------------------------
__global__ void f2h4_kernel(const float* __restrict__ i0, __half* __restrict__ o0,
                            const float* __restrict__ i1, __half* __restrict__ o1,
                            const float* __restrict__ i2, __half* __restrict__ o2,
                            const float* __restrict__ i3, __half* __restrict__ o3,
                            size_t n4)
{
    size_t i = (size_t)blockIdx.x*blockDim.x + threadIdx.x;
    if (i >= n4) return;
    const float* in = (blockIdx.y==0)?i0:(blockIdx.y==1)?i1:(blockIdx.y==2)?i2:i3;
    __half* out     = (blockIdx.y==0)?o0:(blockIdx.y==1)?o1:(blockIdx.y==2)?o2:o3;
    float4 v = ((const float4*)in)[i];
    ((__half2*)out)[i*2  ] = __floats2half2_rn(v.x, v.y);
    ((__half2*)out)[i*2+1] = __floats2half2_rn(v.z, v.w);
}

// ---------------------------------------------------------------------------
// 8 lora-weight transposes in ONE launch; out[c2*Rs + r2]
// ---------------------------------------------------------------------------
__device__ __forceinline__
void transpose_body(const float* __restrict__ in, __half* __restrict__ out,
                    int R, int C, int Rs)
{
    __shared__ float tile[32][33];
    int cb = blockIdx.x*32, rb = blockIdx.y*32;
    if (cb >= C || rb >= R) return;
    int c = cb + threadIdx.x;
    #pragma unroll
    for (int i=threadIdx.y; i<32; i+=8){
        int r = rb + i;
        if (r<R && c<C) tile[i][threadIdx.x] = in[(size_t)r*C + c];
    }
    __syncthreads();
    int r2 = rb + threadIdx.x;
    #pragma unroll
    for (int i=threadIdx.y; i<32; i+=8){
        int c2 = cb + i;
        if (r2<R && c2<C) out[(size_t)c2*Rs + r2] = __float2half_rn(tile[threadIdx.x][i]);
    }
}

__global__ void transpose8b(const float* w1, __half* w1h, const float* w2, __half* w2h,
                            const float* a1, __half* a1h, const float* a2, __half* a2h,
                            const float* v1, __half* v1h, const float* v2, __half* v2h,
                            const float* g1, __half* g1h, const float* g2, __half* g2h)
{
    switch(blockIdx.z){
        case 0: transpose_body(w1, w1h, Cq, DW, Cq);  break;
        case 1: transpose_body(w2, w2h, DW, Cq, DW);  break;
        case 2: transpose_body(a1, a1h, Cq, DA, Cq);  break;
        case 3: transpose_body(a2, a2h, DA, Cq, DA);  break;
        case 4: transpose_body(v1, v1h, Cq, DV, Cq);  break;
        case 5: transpose_body(v2, v2h, DV, Cq, DV);  break;
        case 6: transpose_body(g1, g1h, Cq, DG, Cq);  break;
        default: transpose_body(g2, g2h, DG, Cq, DGp); break;
    }
}

// ---------------------------------------------------------------------------
// Token-shift mix -> fp16 outputs (one float4 per thread — measured optimum)
// ---------------------------------------------------------------------------
__global__ void mix_kernel(const float* __restrict__ x,
                           const float* __restrict__ cr, const float* __restrict__ cw,
                           const float* __restrict__ ck, const float* __restrict__ cv,
                           const float* __restrict__ ca, const float* __restrict__ cg,
                           __half* __restrict__ xr, __half* __restrict__ xw,
                           __half* __restrict__ xk, __half* __restrict__ xv,
                           __half* __restrict__ xa, __half* __restrict__ xg)
{
    size_t i4 = (size_t)blockIdx.x*blockDim.x + threadIdx.x;
    size_t n4 = BTC/4;
    if (i4 >= n4) return;
    size_t flat = i4*4;
    int tok = (int)(flat / Cq);
    int t   = tok % Tq;
    const float4* x4 = (const float4*)x;
    float4 xc = x4[i4];
    float4 xp = (t==0) ? make_float4(0,0,0,0) : x4[i4 - Cq/4];
    float4 dx = make_float4(xp.x-xc.x, xp.y-xc.y, xp.z-xc.z, xp.w-xc.w);
    size_t c4 = i4 % (Cq/4);
    #define MIX1(COEF, OUT) { \
        float4 cf = ((const float4*)COEF)[c4]; \
        ((__half2*)OUT)[i4*2  ] = __floats2half2_rn(xc.x + dx.x*cf.x, xc.y + dx.y*cf.y); \
        ((__half2*)OUT)[i4*2+1] = __floats2half2_rn(xc.z + dx.z*cf.z, xc.w + dx.w*cf.w); }
    MIX1(cr, xr) MIX1(cw, xw) MIX1(ck, xk) MIX1(cv, xv) MIX1(ca, xa) MIX1(cg, xg)
    #undef MIX1
}

// ---------------------------------------------------------------------------
// Epilogue transform: 0 none, 1 tanh, 2 sigmoid, 3 w->decay, 4 a-sigm, 5 v-mix
// ---------------------------------------------------------------------------
template<int EPI>
__device__ __forceinline__ float epi_val(float val, int m, int n, int Nd,
                                         const float* __restrict__ bias,
                                         const float* __restrict__ vold,
                                         const float* __restrict__ vfirst)
{
    if (EPI==1) { val = tanhf(val); }
    else if (EPI==2) { val = sigmoidf_(val); }
    else if (EPI==3) {
        float w = bias[n] + val;
        float mneg = -w;
        float sp = fmaxf(mneg,0.f) + log1pf(expf(-fabsf(mneg)));
        float wl = -sp - 0.5f;
        val = expf(-expf(wl));
    }
    else if (EPI==4) { val = sigmoidf_(bias[n] + val); }
    else if (EPI==5) {
        float s  = sigmoidf_(bias[n] + val);
        size_t idx = (size_t)m*Nd + n;
        float vo = vold[idx];
        val = vo + (vfirst[idx] - vo)*s;
    }
    return val;
}

// ---------------------------------------------------------------------------
// fp16 tensor-core GEMM body: C[m,n] = sum_k A[m,k] * B[n,k]
// CTA 128x128, BK=64, 3-stage cp.async ring, ONE __syncthreads per slab.
// ---------------------------------------------------------------------------
#define GST 3
#define ST_HB (128*72*2)
#define ST_BYTES (2*ST_HB)

template<int EPI,int RND>
__device__ __forceinline__
void gemm_body(const __half* __restrict__ A, const __half* __restrict__ Bw,
               void* __restrict__ Cm, int Nd, int Kd,
               const float* __restrict__ bias,
               const float* __restrict__ vold, const float* __restrict__ vfirst)
{
    extern __shared__ __align__(128) char smc[];
    const int tid = threadIdx.x;
    const int lane = tid&31, warp = tid>>5;
    const int bm = blockIdx.y*128, bn = blockIdx.x*128;
    const int wm = (warp&1)*64, wn = (warp>>1)*32;
    const int g = lane>>2, tig = lane&3;
    const uint32_t sbase = (uint32_t)__cvta_generic_to_shared(smc);

    const int arow = wm + (lane&7) + ((lane>>3)&1)*8;
    const int akof = (lane>>4)*8;
    const int brow = wn + (lane&7) + (lane>>4)*8;
    const int bkof = ((lane>>3)&1)*8;

    float acc[4][4][4];
    #pragma unroll
    for (int i=0;i<4;i++)
        #pragma unroll
        for (int j=0;j<4;j++)
            #pragma unroll
            for (int q=0;q<4;q++) acc[i][j][q]=0.f;

    const int NS = Kd >> 6;

    auto loadSlab = [&](int s, int st){
        const uint32_t sb = sbase + st*ST_BYTES;
        const int k0 = s*64;
        #pragma unroll
        for (int i=0;i<4;i++){
            int id  = tid + i*256;
            int row = id>>3, c16 = id&7;
            cpa16(sb + row*144 + c16*16,
                  &A[(size_t)(bm+row)*Kd + k0 + c16*8]);
            cpa16(sb + ST_HB + row*144 + c16*16,
                  &Bw[(size_t)(bn+row)*Kd + k0 + c16*8]);
        }
    };
    auto compute = [&](int st){
        const uint32_t sb = sbase + st*ST_BYTES;
        #pragma unroll
        for (int ks=0; ks<4; ks++){
            uint32_t af[4][4], bf[2][4];
            #pragma unroll
            for (int mt=0;mt<4;mt++)
                ldsm_x4(af[mt], sb + ((arow+mt*16)*72 + akof + ks*16)*2);
            #pragma unroll
            for (int p=0;p<2;p++)
                ldsm_x4(bf[p], sb + ST_HB + ((brow+p*16)*72 + bkof + ks*16)*2);
            #pragma unroll
            for (int mt=0;mt<4;mt++)
                #pragma unroll
                for (int nt=0;nt<4;nt++)
                    mma16(acc[mt][nt], af[mt], &bf[nt>>1][(nt&1)*2]);
        }
    };

    #pragma unroll
    for (int i=0;i<GST-1;i++){
        if (i<NS) loadSlab(i,i);
        asm volatile("cp.async.commit_group;\n");
    }
    int st = 0;
    for (int s=0;s<NS;s++){
        asm volatile("cp.async.wait_group %0;\n" :: "n"(GST-2));
        __syncthreads();
        int ld = s + GST-1;
        if (ld < NS){
            int lst = st + 2; if (lst >= 3) lst -= 3;
            loadSlab(ld, lst);
        }
        asm volatile("cp.async.commit_group;\n");
        compute(st);
        if (++st == 3) st = 0;
    }

    #pragma unroll
    for (int mt=0;mt<4;mt++){
        int r0 = bm + wm + mt*16 + g;
        #pragma unroll
        for (int nt=0;nt<4;nt++){
            int n0 = bn + wn + nt*8 + tig*2;
            if (n0 < Nd){
                float* c = acc[mt][nt];
                float v00 = epi_val<EPI>(c[0], r0,   n0,   Nd, bias, vold, vfirst);
                float v01 = epi_val<EPI>(c[1], r0,   n0+1, Nd, bias, vold, vfirst);
                float v10 = epi_val<EPI>(c[2], r0+8, n0,   Nd, bias, vold, vfirst);
                float v11 = epi_val<EPI>(c[3], r0+8, n0+1, Nd, bias, vold, vfirst);
                if (RND){
                    __half* O = (__half*)Cm;
                    *(__half2*)&O[(size_t)r0*Nd + n0]     = __floats2half2_rn(v00, v01);
                    *(__half2*)&O[(size_t)(r0+8)*Nd + n0] = __floats2half2_rn(v10, v11);
                } else {
                    float* O = (float*)Cm;
                    *(float2*)&O[(size_t)r0*Nd + n0]     = make_float2(v00, v01);
                    *(float2*)&O[(size_t)(r0+8)*Nd + n0] = make_float2(v10, v11);
                }
            }
        }
    }
}

template<int EPI,int RND>
__global__ __launch_bounds__(256,2)
void gemm_h(const __half* __restrict__ A, const __half* __restrict__ Bw,
            void* __restrict__ Cm, int Nd, int Kd,
            const float* __restrict__ bias,
            const float* __restrict__ vold, const float* __restrict__ vfirst)
{
    gemm_body<EPI,RND>(A, Bw, Cm, Nd, Kd, bias, vold, vfirst);
}

// merged r/k/v projections
__global__ __launch_bounds__(256,2)
void gemm_h3(const __half* __restrict__ A0, const __half* __restrict__ B0, float* __restrict__ C0,
             const __half* __restrict__ A1, const __half* __restrict__ B1, float* __restrict__ C1,
             const __half* __restrict__ A2, const __half* __restrict__ B2, float* __restrict__ C2)
{
    const __half* A = (blockIdx.z==0) ? A0 : (blockIdx.z==1) ? A1 : A2;
    const __half* B = (blockIdx.z==0) ? B0 : (blockIdx.z==1) ? B1 : B2;
    float*        C = (blockIdx.z==0) ? C0 : (blockIdx.z==1) ? C1 : C2;
    gemm_body<0,0>(A, B, (void*)C, Cq, Cq, nullptr, nullptr, nullptr);
}

// 4 lora up-projections in ONE launch
__global__ __launch_bounds__(256,2)
void gemm_lora4(const __half* __restrict__ xw, const __half* __restrict__ w1h, __half* __restrict__ tw,
                const __half* __restrict__ xa, const __half* __restrict__ a1h, __half* __restrict__ ta,
                const __half* __restrict__ xv, const __half* __restrict__ v1h, __half* __restrict__ tv,
                const __half* __restrict__ xg, const __half* __restrict__ g1h, __half* __restrict__ tg)
{
    const int bn = blockIdx.x*128;
    switch(blockIdx.z){
        case 0: if (bn >= DW) return; gemm_body<1,1>(xw, w1h, (void*)tw, DW,  Cq, nullptr,nullptr,nullptr); break;
        case 1: if (bn >= DA) return; gemm_body<0,1>(xa, a1h, (void*)ta, DA,  Cq, nullptr,nullptr,nullptr); break;
        case 2: if (bn >= DV) return; gemm_body<0,1>(xv, v1h, (void*)tv, DV,  Cq, nullptr,nullptr,nullptr); break;
        default:                      gemm_body<2,1>(xg, g1h, (void*)tg, DGp, Cq, nullptr,nullptr,nullptr); break;
    }
}

// 4 lora down-projections in ONE launch
__global__ __launch_bounds__(256,2)
void gemm_lorad4(const __half* __restrict__ twh, const __half* __restrict__ w2h, float* __restrict__ dec, const float* __restrict__ w0,
                 const __half* __restrict__ tah, const __half* __restrict__ a2h, float* __restrict__ aB,  const float* __restrict__ a0,
                 const __half* __restrict__ tvh, const __half* __restrict__ v2h, float* __restrict__ vB,  const float* __restrict__ v0,
                 const float* __restrict__ vfirst,
                 const __half* __restrict__ tgh, const __half* __restrict__ g2h, float* __restrict__ gB)
{
    switch(blockIdx.z){
        case 0: gemm_body<3,0>(twh, w2h, (void*)dec, Cq, DW, w0, nullptr, nullptr); break;
        case 1: gemm_body<4,0>(tah, a2h, (void*)aB,  Cq, DA, a0, nullptr, nullptr); break;
        case 2: gemm_body<5,0>(tvh, v2h, (void*)vB,  Cq, DV, v0, vB, vfirst);       break;
        default: gemm_body<0,0>(tgh, g2h, (void*)gB, Cq, DGp, nullptr, nullptr, nullptr); break;
    }
}

// ---------------------------------------------------------------------------
// kk normalize + k transform
// ---------------------------------------------------------------------------
__global__ void kk_kernel(float* __restrict__ k, const float* __restrict__ a,
                          const float* __restrict__ k_k, const float* __restrict__ k_a,
                          float* __restrict__ kk)
{
    int gw   = blockIdx.x*8 + (threadIdx.x>>5);
    int lane = threadIdx.x & 31;
    int m = gw >> 5;
    int h = gw & 31;
    size_t base = (size_t)m*Cq + h*HSq;
    int c0 = h*HSq + lane, c1 = c0 + 32;
    float k0 = k[base+lane], k1 = k[base+lane+32];
    float kk0 = k0*k_k[c0], kk1 = k1*k_k[c1];
    float s = kk0*kk0 + kk1*kk1;
    #pragma unroll
    for (int off=16; off; off>>=1) s += __shfl_xor_sync(0xffffffffu, s, off);
    float inv = 1.0f / fmaxf(sqrtf(s), 1e-12f);
    kk[base+lane]    = kk0*inv;
    kk[base+lane+32] = kk1*inv;
    float a0 = a[base+lane], a1 = a[base+lane+32];
    k[base+lane]    = k0*(1.0f + (a0-1.0f)*k_a[c0]);
    k[base+lane+32] = k1*(1.0f + (a1-1.0f)*k_a[c1]);
}

// ---------------------------------------------------------------------------
// WKV7 scan: 128 threads per (b,h). Thread (i,p) owns state row i (0..63),
// half p (32 cols). Own launch — scan SMs stay exclusive (R13 lesson).
// ---------------------------------------------------------------------------
__global__ __launch_bounds__(128)
void wkv_kernel(const float* __restrict__ r, const float* __restrict__ wd,
                const float* __restrict__ k, const float* __restrict__ v,
                const float* __restrict__ kkp, const float* __restrict__ ap,
                float* __restrict__ y)
{
    const int bh = blockIdx.x;
    const int b = bh >> 5, h = bh & 31;
    const int tid = threadIdx.x;
    const int i = tid >> 1;
    const int p = tid & 1;
    const int role = tid >> 6;
    const int lc   = tid & 63;

    __shared__ __align__(16) float sbuf[2][6][64];

    float st[32];
    #pragma unroll
    for (int j=0;j<32;j++) st[j]=0.f;

    const size_t base = ((size_t)b*Tq)*Cq + (size_t)h*HSq;

    float l0, l1, l2;
    if (role==0){ l0 = r[base+lc];  l1 = v[base+lc];   l2 = wd[base+lc]; }
    else        { l0 = k[base+lc];  l1 = kkp[base+lc]; l2 = ap[base+lc]; }

    size_t o = base;
    for (int t=0; t<Tq; t++){
        const int cur = t&1;

        if (role==0){ sbuf[cur][0][lc]=l0; sbuf[cur][5][lc]=l1; sbuf[cur][1][lc]=l2; }
        else        { sbuf[cur][2][lc]=l0; sbuf[cur][3][lc]=-l1; sbuf[cur][4][lc]=l1*l2; }
        __syncthreads();

        if (t+1 < Tq){
            size_t on = o + Cq;
            if (role==0){ l0 = r[on+lc];  l1 = v[on+lc];   l2 = wd[on+lc]; }
            else        { l0 = k[on+lc];  l1 = kkp[on+lc]; l2 = ap[on+lc]; }
        }

        const float4* A4 = (const float4*)&sbuf[cur][3][p*32];
        float s0=0,s1=0,s2=0,s3=0;
        #pragma unroll
        for (int j=0;j<8;j++){
            float4 a4 = A4[j];
            s0 += st[4*j+0]*a4.x; s1 += st[4*j+1]*a4.y;
            s2 += st[4*j+2]*a4.z; s3 += st[4*j+3]*a4.w;
        }
        float sav = (s0+s1)+(s2+s3);
        sav += __shfl_xor_sync(0xffffffffu, sav, 1);

        const float vv = sbuf[cur][5][i];
        const float4* W4=(const float4*)&sbuf[cur][1][p*32];
        const float4* K4=(const float4*)&sbuf[cur][2][p*32];
        const float4* B4=(const float4*)&sbuf[cur][4][p*32];
        const float4* R4=(const float4*)&sbuf[cur][0][p*32];
        float o0=0,o1=0,o2=0,o3=0;
        #pragma unroll
        for (int j=0;j<8;j++){
            float4 w4=W4[j], k4=K4[j], b4=B4[j], r4=R4[j];
            float t0 = st[4*j+0]*w4.x + vv*k4.x + sav*b4.x;
            float t1 = st[4*j+1]*w4.y + vv*k4.y + sav*b4.y;
            float t2 = st[4*j+2]*w4.z + vv*k4.z + sav*b4.z;
            float t3 = st[4*j+3]*w4.w + vv*k4.w + sav*b4.w;
            st[4*j+0]=t0; st[4*j+1]=t1; st[4*j+2]=t2; st[4*j+3]=t3;
            o0 += t0*r4.x; o1 += t1*r4.y; o2 += t2*r4.z; o3 += t3*r4.w;
        }
        float op = (o0+o1)+(o2+o3);
        op += __shfl_xor_sync(0xffffffffu, op, 1);
        if (p==0) y[o+i] = op;

        o += Cq;
    }
}

// ---------------------------------------------------------------------------
// GroupNorm + bonus + gate -> z (fp16 for Wo gemm)
// ---------------------------------------------------------------------------
__global__ void gn_kernel(const float* __restrict__ y, const float* __restrict__ r,
                          const float* __restrict__ k, const float* __restrict__ v,
                          const float* __restrict__ g,
                          const float* __restrict__ lnw, const float* __restrict__ lnb,
                          const float* __restrict__ r_k, __half* __restrict__ z)
{
    int gw   = blockIdx.x*8 + (threadIdx.x>>5);
    int lane = threadIdx.x & 31;
    int m = gw >> 5;
    int h = gw & 31;
    size_t base = (size_t)m*Cq + h*HSq;
    int c0 = h*HSq + lane, c1 = c0 + 32;
    float y0=y[base+lane], y1=y[base+lane+32];
    float r0=r[base+lane], r1=r[base+lane+32];
    float k0=k[base+lane], k1=k[base+lane+32];
    float sum = y0+y1;
    float sq  = y0*y0 + y1*y1;
    float dot = r0*k0*r_k[c0] + r1*k1*r_k[c1];
    #pragma unroll
    for (int off=16; off; off>>=1) {
        sum += __shfl_xor_sync(0xffffffffu, sum, off);
        sq  += __shfl_xor_sync(0xffffffffu, sq , off);
        dot += __shfl_xor_sync(0xffffffffu, dot, off);
    }
    float mean = sum * (1.0f/64.0f);
    float var  = sq * (1.0f/64.0f) - mean*mean;
    float inv  = rsqrtf(var + EPS_GN);
    float v0=v[base+lane], v1=v[base+lane+32];
    float g0=g[base+lane], g1=g[base+lane+32];
    float z0 = ((y0-mean)*inv*lnw[c0] + lnb[c0] + dot*v0) * g0;
    float z1 = ((y1-mean)*inv*lnw[c1] + lnb[c1] + dot*v1) * g1;
    z[base+lane]    = __float2half_rn(z0);
    z[base+lane+32] = __float2half_rn(z1);
}

// ---------------------------------------------------------------------------
// Host helpers
// ---------------------------------------------------------------------------
#define SMEM_GEMM (GST*ST_BYTES)

template<int EPI,int RND>
static void rg(const __half* A, const __half* Bw, void* C, int Nd, int Kd,
               const float* bias, const float* vold, const float* vfirst)
{
    cudaFuncSetAttribute(gemm_h<EPI,RND>, cudaFuncAttributeMaxDynamicSharedMemorySize,
                         SMEM_GEMM);
    dim3 grid((Nd+127)/128, Mq/128);
    gemm_h<EPI,RND><<<grid, 256, SMEM_GEMM>>>(A, Bw, C, Nd, Kd, bias, vold, vfirst);
}

// ---------------------------------------------------------------------------
// Launch
// ---------------------------------------------------------------------------
extern "C" void kernel_launch(void* const* d_in, const int* in_sizes, int n_in,
                              void* d_out, int out_size)
{
    const float* x       = (const float*)d_in[0];
    const float* v_first = (const float*)d_in[1];
    const float* x_r = (const float*)d_in[2];
    const float* x_w = (const float*)d_in[3];
    const float* x_k = (const float*)d_in[4];
    const float* x_v = (const float*)d_in[5];
    const float* x_a = (const float*)d_in[6];
    const float* x_g = (const float*)d_in[7];
    const float* w0  = (const float*)d_in[8];
    const float* w1  = (const float*)d_in[9];
    const float* w2  = (const float*)d_in[10];
    const float* a0  = (const float*)d_in[11];
    const float* a1  = (const float*)d_in[12];
    const float* a2  = (const float*)d_in[13];
    const float* v0  = (const float*)d_in[14];
    const float* v1  = (const float*)d_in[15];
    const float* v2  = (const float*)d_in[16];
    const float* g1  = (const float*)d_in[17];
    const float* g2  = (const float*)d_in[18];
    const float* k_k = (const float*)d_in[19];
    const float* k_a = (const float*)d_in[20];
    const float* r_k = (const float*)d_in[21];
    const float* Wr  = (const float*)d_in[22];
    const float* Wk  = (const float*)d_in[23];
    const float* Wv  = (const float*)d_in[24];
    const float* Wo  = (const float*)d_in[25];
    const float* lnw = (const float*)d_in[26];
    const float* lnb = (const float*)d_in[27];
    float* out = (float*)d_out;

    __half *xr,*xw,*xk,*xv,*xa,*xg,*zh,*Wrh,*Wkh,*Wvh,*Woh;
    __half *w1h,*w2h,*a1h,*a2h,*v1h,*v2h,*g1h,*g2h,*twh,*tah,*tvh,*tgh;
    float *rB,*kB,*vB,*dec,*aB,*gB,*kkB,*yB;
    cudaGetSymbolAddress((void**)&xr , h_xr);
    cudaGetSymbolAddress((void**)&xw , h_xw);
    cudaGetSymbolAddress((void**)&xk , h_xk);
    cudaGetSymbolAddress((void**)&xv , h_xv);
    cudaGetSymbolAddress((void**)&xa , h_xa);
    cudaGetSymbolAddress((void**)&xg , h_xg);
    cudaGetSymbolAddress((void**)&zh , h_z);
    cudaGetSymbolAddress((void**)&Wrh, h_Wr);
    cudaGetSymbolAddress((void**)&Wkh, h_Wk);
    cudaGetSymbolAddress((void**)&Wvh, h_Wv);
    cudaGetSymbolAddress((void**)&Woh, h_Wo);
    cudaGetSymbolAddress((void**)&w1h, h_w1);
    cudaGetSymbolAddress((void**)&w2h, h_w2);
    cudaGetSymbolAddress((void**)&a1h, h_a1);
    cudaGetSymbolAddress((void**)&a2h, h_a2);
    cudaGetSymbolAddress((void**)&v1h, h_v1);
    cudaGetSymbolAddress((void**)&v2h, h_v2);
    cudaGetSymbolAddress((void**)&g1h, h_g1);
    cudaGetSymbolAddress((void**)&g2h, h_g2);
    cudaGetSymbolAddress((void**)&twh, h_tw);
    cudaGetSymbolAddress((void**)&tah, h_ta);
    cudaGetSymbolAddress((void**)&tvh, h_tv);
    cudaGetSymbolAddress((void**)&tgh, h_tg);
    cudaGetSymbolAddress((void**)&rB , g_r);
    cudaGetSymbolAddress((void**)&kB , g_k);
    cudaGetSymbolAddress((void**)&vB , g_v);
    cudaGetSymbolAddress((void**)&dec, g_dec);
    cudaGetSymbolAddress((void**)&aB , g_a);
    cudaGetSymbolAddress((void**)&gB , g_g);
    cudaGetSymbolAddress((void**)&kkB, g_kk);
    cudaGetSymbolAddress((void**)&yB , g_y);

    // big weights f32->f16 (one launch)
    f2h4_kernel<<<dim3((unsigned)(((size_t)Cq*Cq/4 + 255)/256), 4), 256>>>(
        Wr, Wrh, Wk, Wkh, Wv, Wvh, Wo, Woh, (size_t)Cq*Cq/4);

    // lora weight transposes (one launch; g2 padded to K-stride 256)
    transpose8b<<<dim3(64, 64, 8), dim3(32,8)>>>(w1, w1h, w2, w2h, a1, a1h, a2, a2h,
                                                 v1, v1h, v2, v2h, g1, g1h, g2, g2h);

    // token-shift mixes -> fp16
    mix_kernel<<<(unsigned)((BTC/4 + 255)/256), 256>>>(x, x_r,x_w,x_k,x_v,x_a,x_g,
                                                       xr,xw,xk,xv,xa,xg);

    // merged big projections r/k/v (one launch)
    cudaFuncSetAttribute(gemm_h3, cudaFuncAttributeMaxDynamicSharedMemorySize, SMEM_GEMM);
    gemm_h3<<<dim3(Cq/128, Mq/128, 3), 256, SMEM_GEMM>>>(
        xr, Wrh, rB, xk, Wkh, kB, xv, Wvh, vB);

    // lora up-projections (one launch)
    cudaFuncSetAttribute(gemm_lora4, cudaFuncAttributeMaxDynamicSharedMemorySize, SMEM_GEMM);
    gemm_lora4<<<dim3(2, Mq/128, 4), 256, SMEM_GEMM>>>(
        xw, w1h, twh, xa, a1h, tah, xv, v1h, tvh, xg, g1h, tgh);

    // lora down-projections (one launch; g uses padded K=256)
    cudaFuncSetAttribute(gemm_lorad4, cudaFuncAttributeMaxDynamicSharedMemorySize, SMEM_GEMM);
    gemm_lorad4<<<dim3(Cq/128, Mq/128, 4), 256, SMEM_GEMM>>>(
        twh, w2h, dec, w0, tah, a2h, aB, a0, tvh, v2h, vB, v0, v_first, tgh, g2h, gB);

    // kk normalize + k transform
    kk_kernel<<<Mq*Hq/8, 256>>>(kB, aB, k_k, k_a, kkB);

    // WKV7 scan (own launch; scan SMs exclusive)
    wkv_kernel<<<Bq*Hq, 128>>>(rB, dec, kB, vB, kkB, aB, yB);

    // GroupNorm + bonus + gate -> fp16 z
    gn_kernel<<<Mq*Hq/8, 256>>>(yB, rB, kB, vB, gB, lnw, lnb, r_k, zh);

    // output projection
    rg<0,0>(zh, Woh, out, Cq, Cq, nullptr,nullptr,nullptr);
}

// round 16
// speedup vs baseline: 1.1539x; 1.0012x over previous
#include <cuda_runtime.h>
#include <cuda_fp16.h>
#include <math.h>
#include <stdint.h>

// Problem constants
#define Bq 4
#define Tq 2048
#define Cq 2048
#define Hq 32
#define HSq 64
#define Mq (Bq*Tq)            // 8192 tokens
#define DW 128
#define DA 128
#define DG 224
#define DGp 256               // padded K for g lora (BK=64 divisibility)
#define DV 64
#define EPS_GN 0.00064f

// ---------------------------------------------------------------------------
// Scratch (static device globals; zero-initialized at module load)
// ---------------------------------------------------------------------------
#define BTC ((size_t)Mq*Cq)
__device__ __half h_xr[BTC];
__device__ __half h_xw[BTC];
__device__ __half h_xk[BTC];
__device__ __half h_xv[BTC];
__device__ __half h_xa[BTC];
__device__ __half h_xg[BTC];
__device__ __half h_z [BTC];
__device__ __half h_Wr[(size_t)Cq*Cq];
__device__ __half h_Wk[(size_t)Cq*Cq];
__device__ __half h_Wv[(size_t)Cq*Cq];
__device__ __half h_Wo[(size_t)Cq*Cq];
__device__ __half h_w1[(size_t)128*Cq];
__device__ __half h_w2[(size_t)Cq*DW];
__device__ __half h_a1[(size_t)128*Cq];
__device__ __half h_a2[(size_t)Cq*DA];
__device__ __half h_v1[(size_t)128*Cq];
__device__ __half h_v2[(size_t)Cq*DV];
__device__ __half h_g1[(size_t)DGp*Cq];   // pad rows stay 0
__device__ __half h_g2[(size_t)Cq*DGp];   // pad cols stay 0
__device__ __half h_tw[(size_t)Mq*DW];
__device__ __half h_ta[(size_t)Mq*DA];
__device__ __half h_tv[(size_t)Mq*DV];
__device__ __half h_tg[(size_t)Mq*DGp];   // stride 256
// fp32 intermediates
__device__ float g_r [BTC];
__device__ float g_k [BTC];
__device__ float g_v [BTC];
__device__ float g_dec[BTC];
__device__ float g_a [BTC];
__device__ float g_g [BTC];
__device__ float g_kk[BTC];
__device__ float g_y [BTC];

__device__ __forceinline__ float sigmoidf_(float x){ return 1.0f/(1.0f+expf(-x)); }

__device__ __forceinline__ void cpa16(uint32_t s, const void* g){
    asm volatile("cp.async.cg.shared.global [%0], [%1], 16;\n" :: "r"(s), "l"(g));
}
__device__ __forceinline__ void ldsm_x4(uint32_t* r, uint32_t addr){
    asm volatile("ldmatrix.sync.aligned.m8n8.x4.shared.b16 {%0,%1,%2,%3}, [%4];"
        : "=r"(r[0]),"=r"(r[1]),"=r"(r[2]),"=r"(r[3]) : "r"(addr));
}
__device__ __forceinline__ void mma16(float* c, const uint32_t* a, const uint32_t* b){
    asm volatile("mma.sync.aligned.m16n8k16.row.col.f32.f16.f16.f32 "
        "{%0,%1,%2,%3},{%4,%5,%6,%7},{%8,%9},{%0,%1,%2,%3};\n"
        : "+f"(c[0]),"+f"(c[1]),"+f"(c[2]),"+f"(c[3])
        : "r"(a[0]),"r"(a[1]),"r"(a[2]),"r"(a[3]),"r"(b[0]),"r"(b[1]));
}

// ---------------------------------------------------------------------------
// Merged prep: z 0-3 = f32->f16 weight copies; z 4-11 = lora transposes.
// Both families use 4096 blocks of 256 threads.
// ---------------------------------------------------------------------------
__device__ __forceinline__
void f2h_body(const float* __restrict__ in, __half* __restrict__ out, size_t n4)
{
    size_t i = (size_t)blockIdx.x*256 + threadIdx.x;
    if (i >= n4) return;
    float4 v = ((const float4*)in)[i];
    ((__half2*)out)[i*2  ] = __floats2half2_rn(v.x, v.y);
    ((__half2*)out)[i*2+1] = __floats2half2_rn(v.z, v.w);
}

__device__ __forceinline__
void transpose_body(const float* __restrict__ in, __half* __restrict__ out,
                    int R, int C, int Rs, int cb, int rb)
{
    __shared__ float tile[32][33];
    if (cb >= C || rb >= R) return;
    int tx = threadIdx.x & 31, ty = threadIdx.x >> 5;   // 32 x 8
    int c = cb + tx;
    #pragma unroll
    for (int i=ty; i<32; i+=8){
        int r = rb + i;
        if (r<R && c<C) tile[i][tx] = in[(size_t)r*C + c];
    }
    __syncthreads();
    int r2 = rb + tx;
    #pragma unroll
    for (int i=ty; i<32; i+=8){
        int c2 = cb + i;
        if (r2<R && c2<C) out[(size_t)c2*Rs + r2] = __float2half_rn(tile[tx][i]);
    }
}

__global__ void prep12(const float* Wr, __half* Wrh, const float* Wk, __half* Wkh,
                       const float* Wv, __half* Wvh, const float* Wo, __half* Woh,
                       const float* w1, __half* w1h, const float* w2, __half* w2h,
                       const float* a1, __half* a1h, const float* a2, __half* a2h,
                       const float* v1, __half* v1h, const float* v2, __half* v2h,
                       const float* g1, __half* g1h, const float* g2, __half* g2h)
{
    const size_t n4 = (size_t)Cq*Cq/4;
    const int cb = (blockIdx.x & 63) * 32;
    const int rb = (blockIdx.x >> 6) * 32;
    switch(blockIdx.z){
        case 0:  f2h_body(Wr, Wrh, n4); break;
        case 1:  f2h_body(Wk, Wkh, n4); break;
        case 2:  f2h_body(Wv, Wvh, n4); break;
        case 3:  f2h_body(Wo, Woh, n4); break;
        case 4:  transpose_body(w1, w1h, Cq, DW, Cq,  cb, rb); break;
        case 5:  transpose_body(w2, w2h, DW, Cq, DW,  cb, rb); break;
        case 6:  transpose_body(a1, a1h, Cq, DA, Cq,  cb, rb); break;
        case 7:  transpose_body(a2, a2h, DA, Cq, DA,  cb, rb); break;
        case 8:  transpose_body(v1, v1h, Cq, DV, Cq,  cb, rb); break;
        case 9:  transpose_body(v2, v2h, DV, Cq, DV,  cb, rb); break;
        case 10: transpose_body(g1, g1h, Cq, DG, Cq,  cb, rb); break;
        default: transpose_body(g2, g2h, DG, Cq, DGp, cb, rb); break;
    }
}

// ---------------------------------------------------------------------------
// Token-shift mix -> fp16 outputs (one float4 per thread — measured optimum)
// ---------------------------------------------------------------------------
__global__ void mix_kernel(const float* __restrict__ x,
                           const float* __restrict__ cr, const float* __restrict__ cw,
                           const float* __restrict__ ck, const float* __restrict__ cv,
                           const float* __restrict__ ca, const float* __restrict__ cg,
                           __half* __restrict__ xr, __half* __restrict__ xw,
                           __half* __restrict__ xk, __half* __restrict__ xv,
                           __half* __restrict__ xa, __half* __restrict__ xg)
{
    size_t i4 = (size_t)blockIdx.x*blockDim.x + threadIdx.x;
    size_t n4 = BTC/4;
    if (i4 >= n4) return;
    size_t flat = i4*4;
    int tok = (int)(flat / Cq);
    int t   = tok % Tq;
    const float4* x4 = (const float4*)x;
    float4 xc = x4[i4];
    float4 xp = (t==0) ? make_float4(0,0,0,0) : x4[i4 - Cq/4];
    float4 dx = make_float4(xp.x-xc.x, xp.y-xc.y, xp.z-xc.z, xp.w-xc.w);
    size_t c4 = i4 % (Cq/4);
    #define MIX1(COEF, OUT) { \
        float4 cf = ((const float4*)COEF)[c4]; \
        ((__half2*)OUT)[i4*2  ] = __floats2half2_rn(xc.x + dx.x*cf.x, xc.y + dx.y*cf.y); \
        ((__half2*)OUT)[i4*2+1] = __floats2half2_rn(xc.z + dx.z*cf.z, xc.w + dx.w*cf.w); }
    MIX1(cr, xr) MIX1(cw, xw) MIX1(ck, xk) MIX1(cv, xv) MIX1(ca, xa) MIX1(cg, xg)
    #undef MIX1
}

// ---------------------------------------------------------------------------
// Epilogue transform: 0 none, 1 tanh, 2 sigmoid, 3 w->decay, 4 a-sigm, 5 v-mix
// ---------------------------------------------------------------------------
template<int EPI>
__device__ __forceinline__ float epi_val(float val, int m, int n, int Nd,
                                         const float* __restrict__ bias,
                                         const float* __restrict__ vold,
                                         const float* __restrict__ vfirst)
{
    if (EPI==1) { val = tanhf(val); }
    else if (EPI==2) { val = sigmoidf_(val); }
    else if (EPI==3) {
        float w = bias[n] + val;
        float mneg = -w;
        float sp = fmaxf(mneg,0.f) + log1pf(expf(-fabsf(mneg)));
        float wl = -sp - 0.5f;
        val = expf(-expf(wl));
    }
    else if (EPI==4) { val = sigmoidf_(bias[n] + val); }
    else if (EPI==5) {
        float s  = sigmoidf_(bias[n] + val);
        size_t idx = (size_t)m*Nd + n;
        float vo = vold[idx];
        val = vo + (vfirst[idx] - vo)*s;
    }
    return val;
}

// ---------------------------------------------------------------------------
// fp16 tensor-core GEMM body: C[m,n] = sum_k A[m,k] * B[n,k]
// CTA 128x128, BK=64, 3-stage cp.async ring, ONE __syncthreads per slab.
// ---------------------------------------------------------------------------
#define GST 3
#define ST_HB (128*72*2)
#define ST_BYTES (2*ST_HB)

template<int EPI,int RND>
__device__ __forceinline__
void gemm_body(const __half* __restrict__ A, const __half* __restrict__ Bw,
               void* __restrict__ Cm, int Nd, int Kd,
               const float* __restrict__ bias,
               const float* __restrict__ vold, const float* __restrict__ vfirst)
{
    extern __shared__ __align__(128) char smc[];
    const int tid = threadIdx.x;
    const int lane = tid&31, warp = tid>>5;
    const int bm = blockIdx.y*128, bn = blockIdx.x*128;
    const int wm = (warp&1)*64, wn = (warp>>1)*32;
    const int g = lane>>2, tig = lane&3;
    const uint32_t sbase = (uint32_t)__cvta_generic_to_shared(smc);

    const int arow = wm + (lane&7) + ((lane>>3)&1)*8;
    const int akof = (lane>>4)*8;
    const int brow = wn + (lane&7) + (lane>>4)*8;
    const int bkof = ((lane>>3)&1)*8;

    float acc[4][4][4];
    #pragma unroll
    for (int i=0;i<4;i++)
        #pragma unroll
        for (int j=0;j<4;j++)
            #pragma unroll
            for (int q=0;q<4;q++) acc[i][j][q]=0.f;

    const int NS = Kd >> 6;

    auto loadSlab = [&](int s, int st){
        const uint32_t sb = sbase + st*ST_BYTES;
        const int k0 = s*64;
        #pragma unroll
        for (int i=0;i<4;i++){
            int id  = tid + i*256;
            int row = id>>3, c16 = id&7;
            cpa16(sb + row*144 + c16*16,
                  &A[(size_t)(bm+row)*Kd + k0 + c16*8]);
            cpa16(sb + ST_HB + row*144 + c16*16,
                  &Bw[(size_t)(bn+row)*Kd + k0 + c16*8]);
        }
    };
    auto compute = [&](int st){
        const uint32_t sb = sbase + st*ST_BYTES;
        #pragma unroll
        for (int ks=0; ks<4; ks++){
            uint32_t af[4][4], bf[2][4];
            #pragma unroll
            for (int mt=0;mt<4;mt++)
                ldsm_x4(af[mt], sb + ((arow+mt*16)*72 + akof + ks*16)*2);
            #pragma unroll
            for (int p=0;p<2;p++)
                ldsm_x4(bf[p], sb + ST_HB + ((brow+p*16)*72 + bkof + ks*16)*2);
            #pragma unroll
            for (int mt=0;mt<4;mt++)
                #pragma unroll
                for (int nt=0;nt<4;nt++)
                    mma16(acc[mt][nt], af[mt], &bf[nt>>1][(nt&1)*2]);
        }
    };

    #pragma unroll
    for (int i=0;i<GST-1;i++){
        if (i<NS) loadSlab(i,i);
        asm volatile("cp.async.commit_group;\n");
    }
    int st = 0;
    for (int s=0;s<NS;s++){
        asm volatile("cp.async.wait_group %0;\n" :: "n"(GST-2));
        __syncthreads();
        int ld = s + GST-1;
        if (ld < NS){
            int lst = st + 2; if (lst >= 3) lst -= 3;
            loadSlab(ld, lst);
        }
        asm volatile("cp.async.commit_group;\n");
        compute(st);
        if (++st == 3) st = 0;
    }

    #pragma unroll
    for (int mt=0;mt<4;mt++){
        int r0 = bm + wm + mt*16 + g;
        #pragma unroll
        for (int nt=0;nt<4;nt++){
            int n0 = bn + wn + nt*8 + tig*2;
            if (n0 < Nd){
                float* c = acc[mt][nt];
                float v00 = epi_val<EPI>(c[0], r0,   n0,   Nd, bias, vold, vfirst);
                float v01 = epi_val<EPI>(c[1], r0,   n0+1, Nd, bias, vold, vfirst);
                float v10 = epi_val<EPI>(c[2], r0+8, n0,   Nd, bias, vold, vfirst);
                float v11 = epi_val<EPI>(c[3], r0+8, n0+1, Nd, bias, vold, vfirst);
                if (RND){
                    __half* O = (__half*)Cm;
                    *(__half2*)&O[(size_t)r0*Nd + n0]     = __floats2half2_rn(v00, v01);
                    *(__half2*)&O[(size_t)(r0+8)*Nd + n0] = __floats2half2_rn(v10, v11);
                } else {
                    float* O = (float*)Cm;
                    *(float2*)&O[(size_t)r0*Nd + n0]     = make_float2(v00, v01);
                    *(float2*)&O[(size_t)(r0+8)*Nd + n0] = make_float2(v10, v11);
                }
            }
        }
    }
}

template<int EPI,int RND>
__global__ __launch_bounds__(256,2)
void gemm_h(const __half* __restrict__ A, const __half* __restrict__ Bw,
            void* __restrict__ Cm, int Nd, int Kd,
            const float* __restrict__ bias,
            const float* __restrict__ vold, const float* __restrict__ vfirst)
{
    gemm_body<EPI,RND>(A, Bw, Cm, Nd, Kd, bias, vold, vfirst);
}

// merged r/k/v projections + 4 lora up-projections (all depend only on mix)
__global__ __launch_bounds__(256,2)
void gemm_big7(const __half* __restrict__ xr, const __half* __restrict__ Wrh, float* __restrict__ rB,
               const __half* __restrict__ xk, const __half* __restrict__ Wkh, float* __restrict__ kB,
               const __half* __restrict__ xv, const __half* __restrict__ Wvh, float* __restrict__ vB,
               const __half* __restrict__ xw, const __half* __restrict__ w1h, __half* __restrict__ tw,
               const __half* __restrict__ xa, const __half* __restrict__ a1h, __half* __restrict__ ta,
               const __half* __restrict__ v1x, const __half* __restrict__ v1h, __half* __restrict__ tv,
               const __half* __restrict__ xg, const __half* __restrict__ g1h, __half* __restrict__ tg)
{
    const int bn = blockIdx.x*128;
    switch(blockIdx.z){
        case 0: gemm_body<0,0>(xr, Wrh, (void*)rB, Cq, Cq, nullptr,nullptr,nullptr); break;
        case 1: gemm_body<0,0>(xk, Wkh, (void*)kB, Cq, Cq, nullptr,nullptr,nullptr); break;
        case 2: gemm_body<0,0>(xv, Wvh, (void*)vB, Cq, Cq, nullptr,nullptr,nullptr); break;
        case 3: if (bn >= DW)  return; gemm_body<1,1>(xw,  w1h, (void*)tw, DW,  Cq, nullptr,nullptr,nullptr); break;
        case 4: if (bn >= DA)  return; gemm_body<0,1>(xa,  a1h, (void*)ta, DA,  Cq, nullptr,nullptr,nullptr); break;
        case 5: if (bn >= DV)  return; gemm_body<0,1>(v1x, v1h, (void*)tv, DV,  Cq, nullptr,nullptr,nullptr); break;
        default: if (bn >= DGp) return; gemm_body<2,1>(xg,  g1h, (void*)tg, DGp, Cq, nullptr,nullptr,nullptr); break;
    }
}

// 4 lora down-projections in ONE launch
__global__ __launch_bounds__(256,2)
void gemm_lorad4(const __half* __restrict__ twh, const __half* __restrict__ w2h, float* __restrict__ dec, const float* __restrict__ w0,
                 const __half* __restrict__ tah, const __half* __restrict__ a2h, float* __restrict__ aB,  const float* __restrict__ a0,
                 const __half* __restrict__ tvh, const __half* __restrict__ v2h, float* __restrict__ vB,  const float* __restrict__ v0,
                 const float* __restrict__ vfirst,
                 const __half* __restrict__ tgh, const __half* __restrict__ g2h, float* __restrict__ gB)
{
    switch(blockIdx.z){
        case 0: gemm_body<3,0>(twh, w2h, (void*)dec, Cq, DW, w0, nullptr, nullptr); break;
        case 1: gemm_body<4,0>(tah, a2h, (void*)aB,  Cq, DA, a0, nullptr, nullptr); break;
        case 2: gemm_body<5,0>(tvh, v2h, (void*)vB,  Cq, DV, v0, vB, vfirst);       break;
        default: gemm_body<0,0>(tgh, g2h, (void*)gB, Cq, DGp, nullptr, nullptr, nullptr); break;
    }
}

// ---------------------------------------------------------------------------
// kk normalize + k transform
// ---------------------------------------------------------------------------
__global__ void kk_kernel(float* __restrict__ k, const float* __restrict__ a,
                          const float* __restrict__ k_k, const float* __restrict__ k_a,
                          float* __restrict__ kk)
{
    int gw   = blockIdx.x*8 + (threadIdx.x>>5);
    int lane = threadIdx.x & 31;
    int m = gw >> 5;
    int h = gw & 31;
    size_t base = (size_t)m*Cq + h*HSq;
    int c0 = h*HSq + lane, c1 = c0 + 32;
    float k0 = k[base+lane], k1 = k[base+lane+32];
    float kk0 = k0*k_k[c0], kk1 = k1*k_k[c1];
    float s = kk0*kk0 + kk1*kk1;
    #pragma unroll
    for (int off=16; off; off>>=1) s += __shfl_xor_sync(0xffffffffu, s, off);
    float inv = 1.0f / fmaxf(sqrtf(s), 1e-12f);
    kk[base+lane]    = kk0*inv;
    kk[base+lane+32] = kk1*inv;
    float a0 = a[base+lane], a1 = a[base+lane+32];
    k[base+lane]    = k0*(1.0f + (a0-1.0f)*k_a[c0]);
    k[base+lane+32] = k1*(1.0f + (a1-1.0f)*k_a[c1]);
}

// ---------------------------------------------------------------------------
// WKV7 scan: 128 threads per (b,h). Thread (i,p) owns state row i (0..63),
// half p (32 cols). Own launch — scan SMs stay exclusive (R13 lesson).
// ---------------------------------------------------------------------------
__global__ __launch_bounds__(128)
void wkv_kernel(const float* __restrict__ r, const float* __restrict__ wd,
                const float* __restrict__ k, const float* __restrict__ v,
                const float* __restrict__ kkp, const float* __restrict__ ap,
                float* __restrict__ y)
{
    const int bh = blockIdx.x;
    const int b = bh >> 5, h = bh & 31;
    const int tid = threadIdx.x;
    const int i = tid >> 1;
    const int p = tid & 1;
    const int role = tid >> 6;
    const int lc   = tid & 63;

    __shared__ __align__(16) float sbuf[2][6][64];

    float st[32];
    #pragma unroll
    for (int j=0;j<32;j++) st[j]=0.f;

    const size_t base = ((size_t)b*Tq)*Cq + (size_t)h*HSq;

    float l0, l1, l2;
    if (role==0){ l0 = r[base+lc];  l1 = v[base+lc];   l2 = wd[base+lc]; }
    else        { l0 = k[base+lc];  l1 = kkp[base+lc]; l2 = ap[base+lc]; }

    size_t o = base;
    for (int t=0; t<Tq; t++){
        const int cur = t&1;

        if (role==0){ sbuf[cur][0][lc]=l0; sbuf[cur][5][lc]=l1; sbuf[cur][1][lc]=l2; }
        else        { sbuf[cur][2][lc]=l0; sbuf[cur][3][lc]=-l1; sbuf[cur][4][lc]=l1*l2; }
        __syncthreads();

        if (t+1 < Tq){
            size_t on = o + Cq;
            if (role==0){ l0 = r[on+lc];  l1 = v[on+lc];   l2 = wd[on+lc]; }
            else        { l0 = k[on+lc];  l1 = kkp[on+lc]; l2 = ap[on+lc]; }
        }

        const float4* A4 = (const float4*)&sbuf[cur][3][p*32];
        float s0=0,s1=0,s2=0,s3=0;
        #pragma unroll
        for (int j=0;j<8;j++){
            float4 a4 = A4[j];
            s0 += st[4*j+0]*a4.x; s1 += st[4*j+1]*a4.y;
            s2 += st[4*j+2]*a4.z; s3 += st[4*j+3]*a4.w;
        }
        float sav = (s0+s1)+(s2+s3);
        sav += __shfl_xor_sync(0xffffffffu, sav, 1);

        const float vv = sbuf[cur][5][i];
        const float4* W4=(const float4*)&sbuf[cur][1][p*32];
        const float4* K4=(const float4*)&sbuf[cur][2][p*32];
        const float4* B4=(const float4*)&sbuf[cur][4][p*32];
        const float4* R4=(const float4*)&sbuf[cur][0][p*32];
        float o0=0,o1=0,o2=0,o3=0;
        #pragma unroll
        for (int j=0;j<8;j++){
            float4 w4=W4[j], k4=K4[j], b4=B4[j], r4=R4[j];
            float t0 = st[4*j+0]*w4.x + vv*k4.x + sav*b4.x;
            float t1 = st[4*j+1]*w4.y + vv*k4.y + sav*b4.y;
            float t2 = st[4*j+2]*w4.z + vv*k4.z + sav*b4.z;
            float t3 = st[4*j+3]*w4.w + vv*k4.w + sav*b4.w;
            st[4*j+0]=t0; st[4*j+1]=t1; st[4*j+2]=t2; st[4*j+3]=t3;
            o0 += t0*r4.x; o1 += t1*r4.y; o2 += t2*r4.z; o3 += t3*r4.w;
        }
        float op = (o0+o1)+(o2+o3);
        op += __shfl_xor_sync(0xffffffffu, op, 1);
        if (p==0) y[o+i] = op;

        o += Cq;
    }
}

// ---------------------------------------------------------------------------
// GroupNorm + bonus + gate -> z (fp16 for Wo gemm)
// ---------------------------------------------------------------------------
__global__ void gn_kernel(const float* __restrict__ y, const float* __restrict__ r,
                          const float* __restrict__ k, const float* __restrict__ v,
                          const float* __restrict__ g,
                          const float* __restrict__ lnw, const float* __restrict__ lnb,
                          const float* __restrict__ r_k, __half* __restrict__ z)
{
    int gw   = blockIdx.x*8 + (threadIdx.x>>5);
    int lane = threadIdx.x & 31;
    int m = gw >> 5;
    int h = gw & 31;
    size_t base = (size_t)m*Cq + h*HSq;
    int c0 = h*HSq + lane, c1 = c0 + 32;
    float y0=y[base+lane], y1=y[base+lane+32];
    float r0=r[base+lane], r1=r[base+lane+32];
    float k0=k[base+lane], k1=k[base+lane+32];
    float sum = y0+y1;
    float sq  = y0*y0 + y1*y1;
    float dot = r0*k0*r_k[c0] + r1*k1*r_k[c1];
    #pragma unroll
    for (int off=16; off; off>>=1) {
        sum += __shfl_xor_sync(0xffffffffu, sum, off);
        sq  += __shfl_xor_sync(0xffffffffu, sq , off);
        dot += __shfl_xor_sync(0xffffffffu, dot, off);
    }
    float mean = sum * (1.0f/64.0f);
    float var  = sq * (1.0f/64.0f) - mean*mean;
    float inv  = rsqrtf(var + EPS_GN);
    float v0=v[base+lane], v1=v[base+lane+32];
    float g0=g[base+lane], g1=g[base+lane+32];
    float z0 = ((y0-mean)*inv*lnw[c0] + lnb[c0] + dot*v0) * g0;
    float z1 = ((y1-mean)*inv*lnw[c1] + lnb[c1] + dot*v1) * g1;
    z[base+lane]    = __float2half_rn(z0);
    z[base+lane+32] = __float2half_rn(z1);
}

// ---------------------------------------------------------------------------
// Host helpers
// ---------------------------------------------------------------------------
#define SMEM_GEMM (GST*ST_BYTES)

template<int EPI,int RND>
static void rg(const __half* A, const __half* Bw, void* C, int Nd, int Kd,
               const float* bias, const float* vold, const float* vfirst)
{
    cudaFuncSetAttribute(gemm_h<EPI,RND>, cudaFuncAttributeMaxDynamicSharedMemorySize,
                         SMEM_GEMM);
    dim3 grid((Nd+127)/128, Mq/128);
    gemm_h<EPI,RND><<<grid, 256, SMEM_GEMM>>>(A, Bw, C, Nd, Kd, bias, vold, vfirst);
}

// ---------------------------------------------------------------------------
// Launch
// ---------------------------------------------------------------------------
extern "C" void kernel_launch(void* const* d_in, const int* in_sizes, int n_in,
                              void* d_out, int out_size)
{
    const float* x       = (const float*)d_in[0];
    const float* v_first = (const float*)d_in[1];
    const float* x_r = (const float*)d_in[2];
    const float* x_w = (const float*)d_in[3];
    const float* x_k = (const float*)d_in[4];
    const float* x_v = (const float*)d_in[5];
    const float* x_a = (const float*)d_in[6];
    const float* x_g = (const float*)d_in[7];
    const float* w0  = (const float*)d_in[8];
    const float* w1  = (const float*)d_in[9];
    const float* w2  = (const float*)d_in[10];
    const float* a0  = (const float*)d_in[11];
    const float* a1  = (const float*)d_in[12];
    const float* a2  = (const float*)d_in[13];
    const float* v0  = (const float*)d_in[14];
    const float* v1  = (const float*)d_in[15];
    const float* v2  = (const float*)d_in[16];
    const float* g1  = (const float*)d_in[17];
    const float* g2  = (const float*)d_in[18];
    const float* k_k = (const float*)d_in[19];
    const float* k_a = (const float*)d_in[20];
    const float* r_k = (const float*)d_in[21];
    const float* Wr  = (const float*)d_in[22];
    const float* Wk  = (const float*)d_in[23];
    const float* Wv  = (const float*)d_in[24];
    const float* Wo  = (const float*)d_in[25];
    const float* lnw = (const float*)d_in[26];
    const float* lnb = (const float*)d_in[27];
    float* out = (float*)d_out;

    __half *xr,*xw,*xk,*xv,*xa,*xg,*zh,*Wrh,*Wkh,*Wvh,*Woh;
    __half *w1h,*w2h,*a1h,*a2h,*v1h,*v2h,*g1h,*g2h,*twh,*tah,*tvh,*tgh;
    float *rB,*kB,*vB,*dec,*aB,*gB,*kkB,*yB;
    cudaGetSymbolAddress((void**)&xr , h_xr);
    cudaGetSymbolAddress((void**)&xw , h_xw);
    cudaGetSymbolAddress((void**)&xk , h_xk);
    cudaGetSymbolAddress((void**)&xv , h_xv);
    cudaGetSymbolAddress((void**)&xa , h_xa);
    cudaGetSymbolAddress((void**)&xg , h_xg);
    cudaGetSymbolAddress((void**)&zh , h_z);
    cudaGetSymbolAddress((void**)&Wrh, h_Wr);
    cudaGetSymbolAddress((void**)&Wkh, h_Wk);
    cudaGetSymbolAddress((void**)&Wvh, h_Wv);
    cudaGetSymbolAddress((void**)&Woh, h_Wo);
    cudaGetSymbolAddress((void**)&w1h, h_w1);
    cudaGetSymbolAddress((void**)&w2h, h_w2);
    cudaGetSymbolAddress((void**)&a1h, h_a1);
    cudaGetSymbolAddress((void**)&a2h, h_a2);
    cudaGetSymbolAddress((void**)&v1h, h_v1);
    cudaGetSymbolAddress((void**)&v2h, h_v2);
    cudaGetSymbolAddress((void**)&g1h, h_g1);
    cudaGetSymbolAddress((void**)&g2h, h_g2);
    cudaGetSymbolAddress((void**)&twh, h_tw);
    cudaGetSymbolAddress((void**)&tah, h_ta);
    cudaGetSymbolAddress((void**)&tvh, h_tv);
    cudaGetSymbolAddress((void**)&tgh, h_tg);
    cudaGetSymbolAddress((void**)&rB , g_r);
    cudaGetSymbolAddress((void**)&kB , g_k);
    cudaGetSymbolAddress((void**)&vB , g_v);
    cudaGetSymbolAddress((void**)&dec, g_dec);
    cudaGetSymbolAddress((void**)&aB , g_a);
    cudaGetSymbolAddress((void**)&gB , g_g);
    cudaGetSymbolAddress((void**)&kkB, g_kk);
    cudaGetSymbolAddress((void**)&yB , g_y);

    // merged prep: weight f2h + lora transposes (one launch)
    prep12<<<dim3(4096, 1, 12), 256>>>(Wr, Wrh, Wk, Wkh, Wv, Wvh, Wo, Woh,
                                       w1, w1h, w2, w2h, a1, a1h, a2, a2h,
                                       v1, v1h, v2, v2h, g1, g1h, g2, g2h);

    // token-shift mixes -> fp16
    mix_kernel<<<(unsigned)((BTC/4 + 255)/256), 256>>>(x, x_r,x_w,x_k,x_v,x_a,x_g,
                                                       xr,xw,xk,xv,xa,xg);

    // merged r/k/v + lora up-projections (one launch, z=0..6)
    cudaFuncSetAttribute(gemm_big7, cudaFuncAttributeMaxDynamicSharedMemorySize, SMEM_GEMM);
    gemm_big7<<<dim3(Cq/128, Mq/128, 7), 256, SMEM_GEMM>>>(
        xr, Wrh, rB, xk, Wkh, kB, xv, Wvh, vB,
        xw, w1h, twh, xa, a1h, tah, xv, v1h, tvh, xg, g1h, tgh);

    // lora down-projections (one launch; g uses padded K=256)
    cudaFuncSetAttribute(gemm_lorad4, cudaFuncAttributeMaxDynamicSharedMemorySize, SMEM_GEMM);
    gemm_lorad4<<<dim3(Cq/128, Mq/128, 4), 256, SMEM_GEMM>>>(
        twh, w2h, dec, w0, tah, a2h, aB, a0, tvh, v2h, vB, v0, v_first, tgh, g2h, gB);

    // kk normalize + k transform
    kk_kernel<<<Mq*Hq/8, 256>>>(kB, aB, k_k, k_a, kkB);

    // WKV7 scan (own launch; scan SMs exclusive)
    wkv_kernel<<<Bq*Hq, 128>>>(rB, dec, kB, vB, kkB, aB, yB);

    // GroupNorm + bonus + gate -> fp16 z
    gn_kernel<<<Mq*Hq/8, 256>>>(yB, rB, kB, vB, gB, lnw, lnb, r_k, zh);

    // output projection
    rg<0,0>(zh, Woh, out, Cq, Cq, nullptr,nullptr,nullptr);
}

// round 17
// speedup vs baseline: 1.1634x; 1.0082x over previous
#include <cuda_runtime.h>
#include <cuda_fp16.h>
#include <math.h>
#include <stdint.h>

// Problem constants
#define Bq 4
#define Tq 2048
#define Cq 2048
#define Hq 32
#define HSq 64
#define Mq (Bq*Tq)            // 8192 tokens
#define DW 128
#define DA 128
#define DG 224
#define DGp 256               // padded K for g lora (BK=64 divisibility)
#define DV 64
#define EPS_GN 0.00064f

// ---------------------------------------------------------------------------
// Scratch (static device globals; zero-initialized at module load)
// ---------------------------------------------------------------------------
#define BTC ((size_t)Mq*Cq)
__device__ __half h_xr[BTC];
__device__ __half h_xw[BTC];
__device__ __half h_xk[BTC];
__device__ __half h_xv[BTC];
__device__ __half h_xa[BTC];
__device__ __half h_xg[BTC];
__device__ __half h_z [BTC];
__device__ __half h_Wr[(size_t)Cq*Cq];
__device__ __half h_Wk[(size_t)Cq*Cq];
__device__ __half h_Wv[(size_t)Cq*Cq];
__device__ __half h_Wo[(size_t)Cq*Cq];
__device__ __half h_w1[(size_t)128*Cq];
__device__ __half h_w2[(size_t)Cq*DW];
__device__ __half h_a1[(size_t)128*Cq];
__device__ __half h_a2[(size_t)Cq*DA];
__device__ __half h_v1[(size_t)128*Cq];
__device__ __half h_v2[(size_t)Cq*DV];
__device__ __half h_g1[(size_t)DGp*Cq];   // pad rows stay 0
__device__ __half h_g2[(size_t)Cq*DGp];   // pad cols stay 0
__device__ __half h_tw[(size_t)Mq*DW];
__device__ __half h_ta[(size_t)Mq*DA];
__device__ __half h_tv[(size_t)Mq*DV];
__device__ __half h_tg[(size_t)Mq*DGp];   // stride 256
// fp32 intermediates
__device__ float g_r [BTC];
__device__ float g_k [BTC];
__device__ float g_v [BTC];
__device__ float g_dec[BTC];
__device__ float g_a [BTC];
__device__ float g_g [BTC];
__device__ float g_kk[BTC];
__device__ float g_y [BTC];

__device__ __forceinline__ float sigmoidf_(float x){ return 1.0f/(1.0f+expf(-x)); }

__device__ __forceinline__ void cpa16(uint32_t s, const void* g){
    asm volatile("cp.async.cg.shared.global [%0], [%1], 16;\n" :: "r"(s), "l"(g));
}
__device__ __forceinline__ void ldsm_x4(uint32_t* r, uint32_t addr){
    asm volatile("ldmatrix.sync.aligned.m8n8.x4.shared.b16 {%0,%1,%2,%3}, [%4];"
        : "=r"(r[0]),"=r"(r[1]),"=r"(r[2]),"=r"(r[3]) : "r"(addr));
}
__device__ __forceinline__ void mma16(float* c, const uint32_t* a, const uint32_t* b){
    asm volatile("mma.sync.aligned.m16n8k16.row.col.f32.f16.f16.f32 "
        "{%0,%1,%2,%3},{%4,%5,%6,%7},{%8,%9},{%0,%1,%2,%3};\n"
        : "+f"(c[0]),"+f"(c[1]),"+f"(c[2]),"+f"(c[3])
        : "r"(a[0]),"r"(a[1]),"r"(a[2]),"r"(a[3]),"r"(b[0]),"r"(b[1]));
}

// ---------------------------------------------------------------------------
// Merged prep: z 0-3 = f32->f16 weight copies; z 4-11 = lora transposes.
// ---------------------------------------------------------------------------
__device__ __forceinline__
void f2h_body(const float* __restrict__ in, __half* __restrict__ out, size_t n4)
{
    size_t i = (size_t)blockIdx.x*256 + threadIdx.x;
    if (i >= n4) return;
    float4 v = ((const float4*)in)[i];
    ((__half2*)out)[i*2  ] = __floats2half2_rn(v.x, v.y);
    ((__half2*)out)[i*2+1] = __floats2half2_rn(v.z, v.w);
}

__device__ __forceinline__
void transpose_body(const float* __restrict__ in, __half* __restrict__ out,
                    int R, int C, int Rs, int cb, int rb)
{
    __shared__ float tile[32][33];
    if (cb >= C || rb >= R) return;
    int tx = threadIdx.x & 31, ty = threadIdx.x >> 5;   // 32 x 8
    int c = cb + tx;
    #pragma unroll
    for (int i=ty; i<32; i+=8){
        int r = rb + i;
        if (r<R && c<C) tile[i][tx] = in[(size_t)r*C + c];
    }
    __syncthreads();
    int r2 = rb + tx;
    #pragma unroll
    for (int i=ty; i<32; i+=8){
        int c2 = cb + i;
        if (r2<R && c2<C) out[(size_t)c2*Rs + r2] = __float2half_rn(tile[tx][i]);
    }
}

__global__ void prep12(const float* Wr, __half* Wrh, const float* Wk, __half* Wkh,
                       const float* Wv, __half* Wvh, const float* Wo, __half* Woh,
                       const float* w1, __half* w1h, const float* w2, __half* w2h,
                       const float* a1, __half* a1h, const float* a2, __half* a2h,
                       const float* v1, __half* v1h, const float* v2, __half* v2h,
                       const float* g1, __half* g1h, const float* g2, __half* g2h)
{
    const size_t n4 = (size_t)Cq*Cq/4;
    const int cb = (blockIdx.x & 63) * 32;
    const int rb = (blockIdx.x >> 6) * 32;
    switch(blockIdx.z){
        case 0:  f2h_body(Wr, Wrh, n4); break;
        case 1:  f2h_body(Wk, Wkh, n4); break;
        case 2:  f2h_body(Wv, Wvh, n4); break;
        case 3:  f2h_body(Wo, Woh, n4); break;
        case 4:  transpose_body(w1, w1h, Cq, DW, Cq,  cb, rb); break;
        case 5:  transpose_body(w2, w2h, DW, Cq, DW,  cb, rb); break;
        case 6:  transpose_body(a1, a1h, Cq, DA, Cq,  cb, rb); break;
        case 7:  transpose_body(a2, a2h, DA, Cq, DA,  cb, rb); break;
        case 8:  transpose_body(v1, v1h, Cq, DV, Cq,  cb, rb); break;
        case 9:  transpose_body(v2, v2h, DV, Cq, DV,  cb, rb); break;
        case 10: transpose_body(g1, g1h, Cq, DG, Cq,  cb, rb); break;
        default: transpose_body(g2, g2h, DG, Cq, DGp, cb, rb); break;
    }
}

// ---------------------------------------------------------------------------
// Token-shift mix -> fp16 outputs (one float4 per thread — measured optimum)
// ---------------------------------------------------------------------------
__global__ void mix_kernel(const float* __restrict__ x,
                           const float* __restrict__ cr, const float* __restrict__ cw,
                           const float* __restrict__ ck, const float* __restrict__ cv,
                           const float* __restrict__ ca, const float* __restrict__ cg,
                           __half* __restrict__ xr, __half* __restrict__ xw,
                           __half* __restrict__ xk, __half* __restrict__ xv,
                           __half* __restrict__ xa, __half* __restrict__ xg)
{
    size_t i4 = (size_t)blockIdx.x*blockDim.x + threadIdx.x;
    size_t n4 = BTC/4;
    if (i4 >= n4) return;
    size_t flat = i4*4;
    int tok = (int)(flat / Cq);
    int t   = tok % Tq;
    const float4* x4 = (const float4*)x;
    float4 xc = x4[i4];
    float4 xp = (t==0) ? make_float4(0,0,0,0) : x4[i4 - Cq/4];
    float4 dx = make_float4(xp.x-xc.x, xp.y-xc.y, xp.z-xc.z, xp.w-xc.w);
    size_t c4 = i4 % (Cq/4);
    #define MIX1(COEF, OUT) { \
        float4 cf = ((const float4*)COEF)[c4]; \
        ((__half2*)OUT)[i4*2  ] = __floats2half2_rn(xc.x + dx.x*cf.x, xc.y + dx.y*cf.y); \
        ((__half2*)OUT)[i4*2+1] = __floats2half2_rn(xc.z + dx.z*cf.z, xc.w + dx.w*cf.w); }
    MIX1(cr, xr) MIX1(cw, xw) MIX1(ck, xk) MIX1(cv, xv) MIX1(ca, xa) MIX1(cg, xg)
    #undef MIX1
}

// ---------------------------------------------------------------------------
// Epilogue transform: 0 none, 1 tanh, 2 sigmoid, 3 w->decay, 4 a-sigm, 5 v-mix
// EPI=3 uses the exact identity exp(-softplus(-w)-1/2) = sigmoid(w)*e^{-1/2}:
//   decay = exp(-exp(-softplus(-w)-0.5)) = exp(-e^{-0.5} * sigmoid(w))
// ---------------------------------------------------------------------------
template<int EPI>
__device__ __forceinline__ float epi_val(float val, int m, int n, int Nd,
                                         const float* __restrict__ bias,
                                         const float* __restrict__ vold,
                                         const float* __restrict__ vfirst)
{
    if (EPI==1) { val = tanhf(val); }
    else if (EPI==2) { val = sigmoidf_(val); }
    else if (EPI==3) {
        float w = bias[n] + val;
        float s = 1.0f/(1.0f+expf(-w));
        val = expf(-0.60653065971263342f * s);
    }
    else if (EPI==4) { val = sigmoidf_(bias[n] + val); }
    else if (EPI==5) {
        float s  = sigmoidf_(bias[n] + val);
        size_t idx = (size_t)m*Nd + n;
        float vo = vold[idx];
        val = vo + (vfirst[idx] - vo)*s;
    }
    return val;
}

// ---------------------------------------------------------------------------
// fp16 tensor-core GEMM body: C[m,n] = sum_k A[m,k] * B[n,k]
// CTA 128x128, BK=64, 3-stage cp.async ring, ONE __syncthreads per slab.
// ---------------------------------------------------------------------------
#define GST 3
#define ST_HB (128*72*2)
#define ST_BYTES (2*ST_HB)

template<int EPI,int RND>
__device__ __forceinline__
void gemm_body(const __half* __restrict__ A, const __half* __restrict__ Bw,
               void* __restrict__ Cm, int Nd, int Kd,
               const float* __restrict__ bias,
               const float* __restrict__ vold, const float* __restrict__ vfirst)
{
    extern __shared__ __align__(128) char smc[];
    const int tid = threadIdx.x;
    const int lane = tid&31, warp = tid>>5;
    const int bm = blockIdx.y*128, bn = blockIdx.x*128;
    const int wm = (warp&1)*64, wn = (warp>>1)*32;
    const int g = lane>>2, tig = lane&3;
    const uint32_t sbase = (uint32_t)__cvta_generic_to_shared(smc);

    const int arow = wm + (lane&7) + ((lane>>3)&1)*8;
    const int akof = (lane>>4)*8;
    const int brow = wn + (lane&7) + (lane>>4)*8;
    const int bkof = ((lane>>3)&1)*8;

    float acc[4][4][4];
    #pragma unroll
    for (int i=0;i<4;i++)
        #pragma unroll
        for (int j=0;j<4;j++)
            #pragma unroll
            for (int q=0;q<4;q++) acc[i][j][q]=0.f;

    const int NS = Kd >> 6;

    auto loadSlab = [&](int s, int st){
        const uint32_t sb = sbase + st*ST_BYTES;
        const int k0 = s*64;
        #pragma unroll
        for (int i=0;i<4;i++){
            int id  = tid + i*256;
            int row = id>>3, c16 = id&7;
            cpa16(sb + row*144 + c16*16,
                  &A[(size_t)(bm+row)*Kd + k0 + c16*8]);
            cpa16(sb + ST_HB + row*144 + c16*16,
                  &Bw[(size_t)(bn+row)*Kd + k0 + c16*8]);
        }
    };
    auto compute = [&](int st){
        const uint32_t sb = sbase + st*ST_BYTES;
        #pragma unroll
        for (int ks=0; ks<4; ks++){
            uint32_t af[4][4], bf[2][4];
            #pragma unroll
            for (int mt=0;mt<4;mt++)
                ldsm_x4(af[mt], sb + ((arow+mt*16)*72 + akof + ks*16)*2);
            #pragma unroll
            for (int p=0;p<2;p++)
                ldsm_x4(bf[p], sb + ST_HB + ((brow+p*16)*72 + bkof + ks*16)*2);
            #pragma unroll
            for (int mt=0;mt<4;mt++)
                #pragma unroll
                for (int nt=0;nt<4;nt++)
                    mma16(acc[mt][nt], af[mt], &bf[nt>>1][(nt&1)*2]);
        }
    };

    #pragma unroll
    for (int i=0;i<GST-1;i++){
        if (i<NS) loadSlab(i,i);
        asm volatile("cp.async.commit_group;\n");
    }
    int st = 0;
    for (int s=0;s<NS;s++){
        asm volatile("cp.async.wait_group %0;\n" :: "n"(GST-2));
        __syncthreads();
        int ld = s + GST-1;
        if (ld < NS){
            int lst = st + 2; if (lst >= 3) lst -= 3;
            loadSlab(ld, lst);
        }
        asm volatile("cp.async.commit_group;\n");
        compute(st);
        if (++st == 3) st = 0;
    }

    #pragma unroll
    for (int mt=0;mt<4;mt++){
        int r0 = bm + wm + mt*16 + g;
        #pragma unroll
        for (int nt=0;nt<4;nt++){
            int n0 = bn + wn + nt*8 + tig*2;
            if (n0 < Nd){
                float* c = acc[mt][nt];
                float v00 = epi_val<EPI>(c[0], r0,   n0,   Nd, bias, vold, vfirst);
                float v01 = epi_val<EPI>(c[1], r0,   n0+1, Nd, bias, vold, vfirst);
                float v10 = epi_val<EPI>(c[2], r0+8, n0,   Nd, bias, vold, vfirst);
                float v11 = epi_val<EPI>(c[3], r0+8, n0+1, Nd, bias, vold, vfirst);
                if (RND){
                    __half* O = (__half*)Cm;
                    *(__half2*)&O[(size_t)r0*Nd + n0]     = __floats2half2_rn(v00, v01);
                    *(__half2*)&O[(size_t)(r0+8)*Nd + n0] = __floats2half2_rn(v10, v11);
                } else {
                    float* O = (float*)Cm;
                    *(float2*)&O[(size_t)r0*Nd + n0]     = make_float2(v00, v01);
                    *(float2*)&O[(size_t)(r0+8)*Nd + n0] = make_float2(v10, v11);
                }
            }
        }
    }
}

template<int EPI,int RND>
__global__ __launch_bounds__(256,2)
void gemm_h(const __half* __restrict__ A, const __half* __restrict__ Bw,
            void* __restrict__ Cm, int Nd, int Kd,
            const float* __restrict__ bias,
            const float* __restrict__ vold, const float* __restrict__ vfirst)
{
    gemm_body<EPI,RND>(A, Bw, Cm, Nd, Kd, bias, vold, vfirst);
}

// merged r/k/v projections + 4 lora up-projections (all depend only on mix)
__global__ __launch_bounds__(256,2)
void gemm_big7(const __half* __restrict__ xr, const __half* __restrict__ Wrh, float* __restrict__ rB,
               const __half* __restrict__ xk, const __half* __restrict__ Wkh, float* __restrict__ kB,
               const __half* __restrict__ xv, const __half* __restrict__ Wvh, float* __restrict__ vB,
               const __half* __restrict__ xw, const __half* __restrict__ w1h, __half* __restrict__ tw,
               const __half* __restrict__ xa, const __half* __restrict__ a1h, __half* __restrict__ ta,
               const __half* __restrict__ v1x, const __half* __restrict__ v1h, __half* __restrict__ tv,
               const __half* __restrict__ xg, const __half* __restrict__ g1h, __half* __restrict__ tg)
{
    const int bn = blockIdx.x*128;
    switch(blockIdx.z){
        case 0: gemm_body<0,0>(xr, Wrh, (void*)rB, Cq, Cq, nullptr,nullptr,nullptr); break;
        case 1: gemm_body<0,0>(xk, Wkh, (void*)kB, Cq, Cq, nullptr,nullptr,nullptr); break;
        case 2: gemm_body<0,0>(xv, Wvh, (void*)vB, Cq, Cq, nullptr,nullptr,nullptr); break;
        case 3: if (bn >= DW)  return; gemm_body<1,1>(xw,  w1h, (void*)tw, DW,  Cq, nullptr,nullptr,nullptr); break;
        case 4: if (bn >= DA)  return; gemm_body<0,1>(xa,  a1h, (void*)ta, DA,  Cq, nullptr,nullptr,nullptr); break;
        case 5: if (bn >= DV)  return; gemm_body<0,1>(v1x, v1h, (void*)tv, DV,  Cq, nullptr,nullptr,nullptr); break;
        default: if (bn >= DGp) return; gemm_body<2,1>(xg,  g1h, (void*)tg, DGp, Cq, nullptr,nullptr,nullptr); break;
    }
}

// 4 lora down-projections in ONE launch (heavy-K first: gate K=256 at z=0)
__global__ __launch_bounds__(256,2)
void gemm_lorad4(const __half* __restrict__ twh, const __half* __restrict__ w2h, float* __restrict__ dec, const float* __restrict__ w0,
                 const __half* __restrict__ tah, const __half* __restrict__ a2h, float* __restrict__ aB,  const float* __restrict__ a0,
                 const __half* __restrict__ tvh, const __half* __restrict__ v2h, float* __restrict__ vB,  const float* __restrict__ v0,
                 const float* __restrict__ vfirst,
                 const __half* __restrict__ tgh, const __half* __restrict__ g2h, float* __restrict__ gB)
{
    switch(blockIdx.z){
        case 0: gemm_body<0,0>(tgh, g2h, (void*)gB, Cq, DGp, nullptr, nullptr, nullptr); break;
        case 1: gemm_body<3,0>(twh, w2h, (void*)dec, Cq, DW, w0, nullptr, nullptr); break;
        case 2: gemm_body<4,0>(tah, a2h, (void*)aB,  Cq, DA, a0, nullptr, nullptr); break;
        default: gemm_body<5,0>(tvh, v2h, (void*)vB, Cq, DV, v0, vB, vfirst);       break;
    }
}

// ---------------------------------------------------------------------------
// kk normalize + k transform
// ---------------------------------------------------------------------------
__global__ void kk_kernel(float* __restrict__ k, const float* __restrict__ a,
                          const float* __restrict__ k_k, const float* __restrict__ k_a,
                          float* __restrict__ kk)
{
    int gw   = blockIdx.x*8 + (threadIdx.x>>5);
    int lane = threadIdx.x & 31;
    int m = gw >> 5;
    int h = gw & 31;
    size_t base = (size_t)m*Cq + h*HSq;
    int c0 = h*HSq + lane, c1 = c0 + 32;
    float k0 = k[base+lane], k1 = k[base+lane+32];
    float kk0 = k0*k_k[c0], kk1 = k1*k_k[c1];
    float s = kk0*kk0 + kk1*kk1;
    #pragma unroll
    for (int off=16; off; off>>=1) s += __shfl_xor_sync(0xffffffffu, s, off);
    float inv = 1.0f / fmaxf(sqrtf(s), 1e-12f);
    kk[base+lane]    = kk0*inv;
    kk[base+lane+32] = kk1*inv;
    float a0 = a[base+lane], a1 = a[base+lane+32];
    k[base+lane]    = k0*(1.0f + (a0-1.0f)*k_a[c0]);
    k[base+lane+32] = k1*(1.0f + (a1-1.0f)*k_a[c1]);
}

// ---------------------------------------------------------------------------
// WKV7 scan: 128 threads per (b,h). Thread (i,p) owns state row i (0..63),
// half p (32 cols). Own launch — scan SMs stay exclusive (R13 lesson).
// ---------------------------------------------------------------------------
__global__ __launch_bounds__(128)
void wkv_kernel(const float* __restrict__ r, const float* __restrict__ wd,
                const float* __restrict__ k, const float* __restrict__ v,
                const float* __restrict__ kkp, const float* __restrict__ ap,
                float* __restrict__ y)
{
    const int bh = blockIdx.x;
    const int b = bh >> 5, h = bh & 31;
    const int tid = threadIdx.x;
    const int i = tid >> 1;
    const int p = tid & 1;
    const int role = tid >> 6;
    const int lc   = tid & 63;

    __shared__ __align__(16) float sbuf[2][6][64];

    float st[32];
    #pragma unroll
    for (int j=0;j<32;j++) st[j]=0.f;

    const size_t base = ((size_t)b*Tq)*Cq + (size_t)h*HSq;

    float l0, l1, l2;
    if (role==0){ l0 = r[base+lc];  l1 = v[base+lc];   l2 = wd[base+lc]; }
    else        { l0 = k[base+lc];  l1 = kkp[base+lc]; l2 = ap[base+lc]; }

    size_t o = base;
    for (int t=0; t<Tq; t++){
        const int cur = t&1;

        if (role==0){ sbuf[cur][0][lc]=l0; sbuf[cur][5][lc]=l1; sbuf[cur][1][lc]=l2; }
        else        { sbuf[cur][2][lc]=l0; sbuf[cur][3][lc]=-l1; sbuf[cur][4][lc]=l1*l2; }
        __syncthreads();

        if (t+1 < Tq){
            size_t on = o + Cq;
            if (role==0){ l0 = r[on+lc];  l1 = v[on+lc];   l2 = wd[on+lc]; }
            else        { l0 = k[on+lc];  l1 = kkp[on+lc]; l2 = ap[on+lc]; }
        }

        const float4* A4 = (const float4*)&sbuf[cur][3][p*32];
        float s0=0,s1=0,s2=0,s3=0;
        #pragma unroll
        for (int j=0;j<8;j++){
            float4 a4 = A4[j];
            s0 += st[4*j+0]*a4.x; s1 += st[4*j+1]*a4.y;
            s2 += st[4*j+2]*a4.z; s3 += st[4*j+3]*a4.w;
        }
        float sav = (s0+s1)+(s2+s3);
        sav += __shfl_xor_sync(0xffffffffu, sav, 1);

        const float vv = sbuf[cur][5][i];
        const float4* W4=(const float4*)&sbuf[cur][1][p*32];
        const float4* K4=(const float4*)&sbuf[cur][2][p*32];
        const float4* B4=(const float4*)&sbuf[cur][4][p*32];
        const float4* R4=(const float4*)&sbuf[cur][0][p*32];
        float o0=0,o1=0,o2=0,o3=0;
        #pragma unroll
        for (int j=0;j<8;j++){
            float4 w4=W4[j], k4=K4[j], b4=B4[j], r4=R4[j];
            float t0 = st[4*j+0]*w4.x + vv*k4.x + sav*b4.x;
            float t1 = st[4*j+1]*w4.y + vv*k4.y + sav*b4.y;
            float t2 = st[4*j+2]*w4.z + vv*k4.z + sav*b4.z;
            float t3 = st[4*j+3]*w4.w + vv*k4.w + sav*b4.w;
            st[4*j+0]=t0; st[4*j+1]=t1; st[4*j+2]=t2; st[4*j+3]=t3;
            o0 += t0*r4.x; o1 += t1*r4.y; o2 += t2*r4.z; o3 += t3*r4.w;
        }
        float op = (o0+o1)+(o2+o3);
        op += __shfl_xor_sync(0xffffffffu, op, 1);
        if (p==0) y[o+i] = op;

        o += Cq;
    }
}

// ---------------------------------------------------------------------------
// GroupNorm + bonus + gate -> z (fp16 for Wo gemm)
// ---------------------------------------------------------------------------
__global__ void gn_kernel(const float* __restrict__ y, const float* __restrict__ r,
                          const float* __restrict__ k, const float* __restrict__ v,
                          const float* __restrict__ g,
                          const float* __restrict__ lnw, const float* __restrict__ lnb,
                          const float* __restrict__ r_k, __half* __restrict__ z)
{
    int gw   = blockIdx.x*8 + (threadIdx.x>>5);
    int lane = threadIdx.x & 31;
    int m = gw >> 5;
    int h = gw & 31;
    size_t base = (size_t)m*Cq + h*HSq;
    int c0 = h*HSq + lane, c1 = c0 + 32;
    float y0=y[base+lane], y1=y[base+lane+32];
    float r0=r[base+lane], r1=r[base+lane+32];
    float k0=k[base+lane], k1=k[base+lane+32];
    float sum = y0+y1;
    float sq  = y0*y0 + y1*y1;
    float dot = r0*k0*r_k[c0] + r1*k1*r_k[c1];
    #pragma unroll
    for (int off=16; off; off>>=1) {
        sum += __shfl_xor_sync(0xffffffffu, sum, off);
        sq  += __shfl_xor_sync(0xffffffffu, sq , off);
        dot += __shfl_xor_sync(0xffffffffu, dot, off);
    }
    float mean = sum * (1.0f/64.0f);
    float var  = sq * (1.0f/64.0f) - mean*mean;
    float inv  = rsqrtf(var + EPS_GN);
    float v0=v[base+lane], v1=v[base+lane+32];
    float g0=g[base+lane], g1=g[base+lane+32];
    float z0 = ((y0-mean)*inv*lnw[c0] + lnb[c0] + dot*v0) * g0;
    float z1 = ((y1-mean)*inv*lnw[c1] + lnb[c1] + dot*v1) * g1;
    z[base+lane]    = __float2half_rn(z0);
    z[base+lane+32] = __float2half_rn(z1);
}

// ---------------------------------------------------------------------------
// Host helpers
// ---------------------------------------------------------------------------
#define SMEM_GEMM (GST*ST_BYTES)

template<int EPI,int RND>
static void rg(const __half* A, const __half* Bw, void* C, int Nd, int Kd,
               const float* bias, const float* vold, const float* vfirst)
{
    cudaFuncSetAttribute(gemm_h<EPI,RND>, cudaFuncAttributeMaxDynamicSharedMemorySize,
                         SMEM_GEMM);
    dim3 grid((Nd+127)/128, Mq/128);
    gemm_h<EPI,RND><<<grid, 256, SMEM_GEMM>>>(A, Bw, C, Nd, Kd, bias, vold, vfirst);
}

// ---------------------------------------------------------------------------
// Launch
// ---------------------------------------------------------------------------
extern "C" void kernel_launch(void* const* d_in, const int* in_sizes, int n_in,
                              void* d_out, int out_size)
{
    const float* x       = (const float*)d_in[0];
    const float* v_first = (const float*)d_in[1];
    const float* x_r = (const float*)d_in[2];
    const float* x_w = (const float*)d_in[3];
    const float* x_k = (const float*)d_in[4];
    const float* x_v = (const float*)d_in[5];
    const float* x_a = (const float*)d_in[6];
    const float* x_g = (const float*)d_in[7];
    const float* w0  = (const float*)d_in[8];
    const float* w1  = (const float*)d_in[9];
    const float* w2  = (const float*)d_in[10];
    const float* a0  = (const float*)d_in[11];
    const float* a1  = (const float*)d_in[12];
    const float* a2  = (const float*)d_in[13];
    const float* v0  = (const float*)d_in[14];
    const float* v1  = (const float*)d_in[15];
    const float* v2  = (const float*)d_in[16];
    const float* g1  = (const float*)d_in[17];
    const float* g2  = (const float*)d_in[18];
    const float* k_k = (const float*)d_in[19];
    const float* k_a = (const float*)d_in[20];
    const float* r_k = (const float*)d_in[21];
    const float* Wr  = (const float*)d_in[22];
    const float* Wk  = (const float*)d_in[23];
    const float* Wv  = (const float*)d_in[24];
    const float* Wo  = (const float*)d_in[25];
    const float* lnw = (const float*)d_in[26];
    const float* lnb = (const float*)d_in[27];
    float* out = (float*)d_out;

    __half *xr,*xw,*xk,*xv,*xa,*xg,*zh,*Wrh,*Wkh,*Wvh,*Woh;
    __half *w1h,*w2h,*a1h,*a2h,*v1h,*v2h,*g1h,*g2h,*twh,*tah,*tvh,*tgh;
    float *rB,*kB,*vB,*dec,*aB,*gB,*kkB,*yB;
    cudaGetSymbolAddress((void**)&xr , h_xr);
    cudaGetSymbolAddress((void**)&xw , h_xw);
    cudaGetSymbolAddress((void**)&xk , h_xk);
    cudaGetSymbolAddress((void**)&xv , h_xv);
    cudaGetSymbolAddress((void**)&xa , h_xa);
    cudaGetSymbolAddress((void**)&xg , h_xg);
    cudaGetSymbolAddress((void**)&zh , h_z);
    cudaGetSymbolAddress((void**)&Wrh, h_Wr);
    cudaGetSymbolAddress((void**)&Wkh, h_Wk);
    cudaGetSymbolAddress((void**)&Wvh, h_Wv);
    cudaGetSymbolAddress((void**)&Woh, h_Wo);
    cudaGetSymbolAddress((void**)&w1h, h_w1);
    cudaGetSymbolAddress((void**)&w2h, h_w2);
    cudaGetSymbolAddress((void**)&a1h, h_a1);
    cudaGetSymbolAddress((void**)&a2h, h_a2);
    cudaGetSymbolAddress((void**)&v1h, h_v1);
    cudaGetSymbolAddress((void**)&v2h, h_v2);
    cudaGetSymbolAddress((void**)&g1h, h_g1);
    cudaGetSymbolAddress((void**)&g2h, h_g2);
    cudaGetSymbolAddress((void**)&twh, h_tw);
    cudaGetSymbolAddress((void**)&tah, h_ta);
    cudaGetSymbolAddress((void**)&tvh, h_tv);
    cudaGetSymbolAddress((void**)&tgh, h_tg);
    cudaGetSymbolAddress((void**)&rB , g_r);
    cudaGetSymbolAddress((void**)&kB , g_k);
    cudaGetSymbolAddress((void**)&vB , g_v);
    cudaGetSymbolAddress((void**)&dec, g_dec);
    cudaGetSymbolAddress((void**)&aB , g_a);
    cudaGetSymbolAddress((void**)&gB , g_g);
    cudaGetSymbolAddress((void**)&kkB, g_kk);
    cudaGetSymbolAddress((void**)&yB , g_y);

    // merged prep: weight f2h + lora transposes (one launch)
    prep12<<<dim3(4096, 1, 12), 256>>>(Wr, Wrh, Wk, Wkh, Wv, Wvh, Wo, Woh,
                                       w1, w1h, w2, w2h, a1, a1h, a2, a2h,
                                       v1, v1h, v2, v2h, g1, g1h, g2, g2h);

    // token-shift mixes -> fp16
    mix_kernel<<<(unsigned)((BTC/4 + 255)/256), 256>>>(x, x_r,x_w,x_k,x_v,x_a,x_g,
                                                       xr,xw,xk,xv,xa,xg);

    // merged r/k/v + lora up-projections (one launch, z=0..6)
    cudaFuncSetAttribute(gemm_big7, cudaFuncAttributeMaxDynamicSharedMemorySize, SMEM_GEMM);
    gemm_big7<<<dim3(Cq/128, Mq/128, 7), 256, SMEM_GEMM>>>(
        xr, Wrh, rB, xk, Wkh, kB, xv, Wvh, vB,
        xw, w1h, twh, xa, a1h, tah, xv, v1h, tvh, xg, g1h, tgh);

    // lora down-projections (one launch; heavy gate K=256 first)
    cudaFuncSetAttribute(gemm_lorad4, cudaFuncAttributeMaxDynamicSharedMemorySize, SMEM_GEMM);
    gemm_lorad4<<<dim3(Cq/128, Mq/128, 4), 256, SMEM_GEMM>>>(
        twh, w2h, dec, w0, tah, a2h, aB, a0, tvh, v2h, vB, v0, v_first, tgh, g2h, gB);

    // kk normalize + k transform
    kk_kernel<<<Mq*Hq/8, 256>>>(kB, aB, k_k, k_a, kkB);

    // WKV7 scan (own launch; scan SMs exclusive)
    wkv_kernel<<<Bq*Hq, 128>>>(rB, dec, kB, vB, kkB, aB, yB);

    // GroupNorm + bonus + gate -> fp16 z
    gn_kernel<<<Mq*Hq/8, 256>>>(yB, rB, kB, vB, gB, lnw, lnb, r_k, zh);

    // output projection
    rg<0,0>(zh, Woh, out, Cq, Cq, nullptr,nullptr,nullptr);
}